// round 10
// baseline (speedup 1.0000x reference)
#include <cuda_runtime.h>
#include <cuda_bf16.h>
#include <math.h>
#include <stdint.h>

#define Bb 16
#define Ss 2048
#define Tt 1024
#define Ee 256
#define Dd 256
#define NSLICE 4
#define SLICE_S 512
#define MTOT (Bb * Tt)   // 16384

// ---------------------------------------------------------------------------
// Scratch (allocation-free device globals), bf16 hi/lo split representations.
// ---------------------------------------------------------------------------
__device__ __nv_bfloat16 g_encH[Bb * Ss * Ee];
__device__ __nv_bfloat16 g_encL[Bb * Ss * Ee];
__device__ __nv_bfloat16 g_decH[Bb * Tt * Dd];
__device__ __nv_bfloat16 g_decL[Bb * Tt * Dd];
__device__ __nv_bfloat16 g_dpH[Bb * Tt * Ee];     // decproj hi
__device__ __nv_bfloat16 g_dpL[Bb * Tt * Ee];     // decproj lo
__device__ __nv_bfloat16 g_WencH[Ee * Dd];        // W_enc native [e][d]
__device__ __nv_bfloat16 g_WencL[Ee * Dd];
__device__ __nv_bfloat16 g_WfinTH[Dd * (Ee + Dd)];
__device__ __nv_bfloat16 g_WfinTL[Dd * (Ee + Dd)];
__device__ int g_lengths[Bb];
__device__ float g_pctx[NSLICE * MTOT * Ee];      // fp32 split-KV partials
__device__ float g_pm[NSLICE * MTOT];
__device__ float g_pl[NSLICE * MTOT];

// ---------------------------------------------------------------------------
// Helpers
// ---------------------------------------------------------------------------
__device__ __forceinline__ uint32_t smem_u32(const void* p) {
    uint32_t a;
    asm("{ .reg .u64 t; cvta.to.shared.u64 t, %1; cvt.u32.u64 %0, t; }"
        : "=r"(a) : "l"(p));
    return a;
}

__device__ __forceinline__ void mma16816(float* d, const uint32_t* a,
                                         const uint32_t* b) {
    asm volatile(
        "mma.sync.aligned.m16n8k16.row.col.f32.bf16.bf16.f32 "
        "{%0,%1,%2,%3}, {%4,%5,%6,%7}, {%8,%9}, {%0,%1,%2,%3};"
        : "+f"(d[0]), "+f"(d[1]), "+f"(d[2]), "+f"(d[3])
        : "r"(a[0]), "r"(a[1]), "r"(a[2]), "r"(a[3]), "r"(b[0]), "r"(b[1]));
}

__device__ __forceinline__ void ldsm_x4_t(uint32_t& r0, uint32_t& r1,
                                          uint32_t& r2, uint32_t& r3,
                                          uint32_t addr) {
    asm volatile("ldmatrix.sync.aligned.m8n8.x4.trans.shared.b16 "
                 "{%0,%1,%2,%3}, [%4];"
                 : "=r"(r0), "=r"(r1), "=r"(r2), "=r"(r3) : "r"(addr));
}

__device__ __forceinline__ void cp16(uint32_t dst, const void* src) {
    asm volatile("cp.async.cg.shared.global [%0], [%1], 16;"
                 :: "r"(dst), "l"(src));
}
#define CP_COMMIT() asm volatile("cp.async.commit_group;")
#define CP_WAIT(N)  asm volatile("cp.async.wait_group %0;" :: "n"(N))

__device__ __forceinline__ void bsplit(float x, unsigned short& h,
                                       unsigned short& l) {
    __nv_bfloat16 hb = __float2bfloat16(x);
    __nv_bfloat16 lb = __float2bfloat16(x - __bfloat162float(hb));
    h = *(unsigned short*)&hb;
    l = *(unsigned short*)&lb;
}

__device__ __forceinline__ uint32_t pack2(unsigned short a, unsigned short b) {
    return (uint32_t)a | ((uint32_t)b << 16);
}

// ---------------------------------------------------------------------------
// Mask prologue (handles uint8 or int32 bool encodings)
// ---------------------------------------------------------------------------
__global__ void detect_lengths_kernel(const unsigned char* __restrict__ mask)
{
    __shared__ int s_flag;
    __shared__ int s_cnt[Bb];
    int tid = threadIdx.x;
    if (tid == 0) s_flag = 0;
    if (tid < Bb) s_cnt[tid] = 0;
    __syncthreads();

    int local = 0;
    for (int i = tid; i < Bb * Ss; i += 256)
        if ((i & 3) != 0 && mask[i] != 0) local = 1;
    if (local) atomicOr(&s_flag, 1);
    __syncthreads();

    bool isU8 = (s_flag != 0);
    int row = tid >> 4, part = tid & 15;
    int cnt = 0;
    if (isU8) {
        const unsigned char* p = mask + row * Ss + part * 128;
        #pragma unroll 4
        for (int e = 0; e < 128; e++) cnt += (p[e] != 0);
    } else {
        const int* p = ((const int*)mask) + row * Ss + part * 128;
        #pragma unroll 4
        for (int e = 0; e < 128; e++) cnt += (p[e] != 0);
    }
    atomicAdd(&s_cnt[row], cnt);
    __syncthreads();
    if (tid < Bb) g_lengths[tid] = s_cnt[tid];
}

// ---------------------------------------------------------------------------
// Prep: fp32 -> bf16 hi/lo for enc, dec; W_enc split; W_fin transposed+split.
// ---------------------------------------------------------------------------
__global__ void prep_convert_kernel(const float* __restrict__ enc,
                                    const float* __restrict__ dec,
                                    const float* __restrict__ Wenc,
                                    const float* __restrict__ Wfin)
{
    int tid = blockIdx.x * blockDim.x + threadIdx.x;
    int stride = gridDim.x * blockDim.x;

    const int NE4 = (Bb * Ss * Ee) / 4;
    for (int i = tid; i < NE4; i += stride) {
        float4 v = ((const float4*)enc)[i];
        ushort4 hv, lv;
        bsplit(v.x, hv.x, lv.x); bsplit(v.y, hv.y, lv.y);
        bsplit(v.z, hv.z, lv.z); bsplit(v.w, hv.w, lv.w);
        ((ushort4*)g_encH)[i] = hv;
        ((ushort4*)g_encL)[i] = lv;
    }
    const int ND4 = (Bb * Tt * Dd) / 4;
    for (int i = tid; i < ND4; i += stride) {
        float4 v = ((const float4*)dec)[i];
        ushort4 hv, lv;
        bsplit(v.x, hv.x, lv.x); bsplit(v.y, hv.y, lv.y);
        bsplit(v.z, hv.z, lv.z); bsplit(v.w, hv.w, lv.w);
        ((ushort4*)g_decH)[i] = hv;
        ((ushort4*)g_decL)[i] = lv;
    }
    for (int i = tid; i < 256 * 256; i += stride) {
        unsigned short h, l;
        bsplit(Wenc[i], h, l);
        *(unsigned short*)&g_WencH[i] = h;
        *(unsigned short*)&g_WencL[i] = l;
    }
    for (int i = tid; i < 256 * 512; i += stride) {
        int d = i >> 9, f = i & 511;
        unsigned short h, l;
        bsplit(Wfin[f * 256 + d], h, l);
        *(unsigned short*)&g_WfinTH[i] = h;
        *(unsigned short*)&g_WfinTL[i] = l;
    }
}

// ---------------------------------------------------------------------------
// Pipelined GEMM smem: 32-wide k-chunks, stride 40 shorts (80 B) per row,
// double-buffered. Buffer = 4 matrices (Ah,Al,Bh,Bl) x 128 rows x 80 B.
// ---------------------------------------------------------------------------
#define PG_MAT   10240          // 128 * 80
#define PG_BUF   (4 * PG_MAT)   // 40960
#define PG_TOTAL (2 * PG_BUF)   // 81920
#define PG_AH 0
#define PG_AL PG_MAT
#define PG_BH (2 * PG_MAT)
#define PG_BL (3 * PG_MAT)

// ---------------------------------------------------------------------------
// GEMM1' (decproj = dec @ W_enc^T), K=256, 8 chunks, cp.async pipelined.
// ---------------------------------------------------------------------------
__global__ __launch_bounds__(256, 2)
void mma_gemm1_kernel(const __nv_bfloat16* __restrict__ A1H,
                      const __nv_bfloat16* __restrict__ A1L,
                      const __nv_bfloat16* __restrict__ BTH,
                      const __nv_bfloat16* __restrict__ BTL,
                      __nv_bfloat16* __restrict__ CH,
                      __nv_bfloat16* __restrict__ CL)
{
    extern __shared__ char dyn[];
    uint32_t base = smem_u32(dyn);

    int tid = threadIdx.x, lane = tid & 31, wid = tid >> 5;
    int warpM = wid & 3, warpN = wid >> 2;
    int m0 = blockIdx.y * 128, n0 = blockIdx.x * 128;
    int r = lane >> 2, cc = (lane & 3) * 2;

    float acc[2][8][4];
    #pragma unroll
    for (int i = 0; i < 2; i++)
        #pragma unroll
        for (int j = 0; j < 8; j++)
            #pragma unroll
            for (int q = 0; q < 4; q++) acc[i][j][q] = 0.f;

    auto stage = [&](int ch, int buf) {
        uint32_t bb = base + buf * PG_BUF;
        int kc = ch * 32;
        #pragma unroll
        for (int u = 0; u < 2; u++) {
            int f = tid + u * 256;
            int rr = f >> 2, c = f & 3;
            uint32_t doff = rr * 80 + c * 16;
            size_t ga = (size_t)(m0 + rr) * 256 + kc + c * 8;
            size_t gb = (size_t)(n0 + rr) * 256 + kc + c * 8;
            cp16(bb + PG_AH + doff, A1H + ga);
            cp16(bb + PG_AL + doff, A1L + ga);
            cp16(bb + PG_BH + doff, BTH + gb);
            cp16(bb + PG_BL + doff, BTL + gb);
        }
    };

    stage(0, 0);
    CP_COMMIT();

    for (int ch = 0; ch < 8; ch++) {
        CP_WAIT(0);
        __syncthreads();
        if (ch < 7) {
            stage(ch + 1, (ch + 1) & 1);
            CP_COMMIT();
        }
        const __nv_bfloat16* sAH =
            (const __nv_bfloat16*)(dyn + (ch & 1) * PG_BUF + PG_AH);
        const __nv_bfloat16* sAL =
            (const __nv_bfloat16*)(dyn + (ch & 1) * PG_BUF + PG_AL);
        const __nv_bfloat16* sBH =
            (const __nv_bfloat16*)(dyn + (ch & 1) * PG_BUF + PG_BH);
        const __nv_bfloat16* sBL =
            (const __nv_bfloat16*)(dyn + (ch & 1) * PG_BUF + PG_BL);

        #pragma unroll
        for (int ks = 0; ks < 2; ks++) {
            int ac = ks * 16 + cc;
            uint32_t aH[2][4], aL[2][4];
            #pragma unroll
            for (int mt = 0; mt < 2; mt++) {
                int ar = warpM * 32 + mt * 16 + r;
                aH[mt][0] = *(uint32_t*)&sAH[ar * 40 + ac];
                aH[mt][1] = *(uint32_t*)&sAH[(ar + 8) * 40 + ac];
                aH[mt][2] = *(uint32_t*)&sAH[ar * 40 + ac + 8];
                aH[mt][3] = *(uint32_t*)&sAH[(ar + 8) * 40 + ac + 8];
                aL[mt][0] = *(uint32_t*)&sAL[ar * 40 + ac];
                aL[mt][1] = *(uint32_t*)&sAL[(ar + 8) * 40 + ac];
                aL[mt][2] = *(uint32_t*)&sAL[ar * 40 + ac + 8];
                aL[mt][3] = *(uint32_t*)&sAL[(ar + 8) * 40 + ac + 8];
            }
            #pragma unroll
            for (int nt = 0; nt < 8; nt++) {
                int bn = warpN * 64 + nt * 8 + r;
                uint32_t bH[2], bL[2];
                bH[0] = *(uint32_t*)&sBH[bn * 40 + ac];
                bH[1] = *(uint32_t*)&sBH[bn * 40 + ac + 8];
                bL[0] = *(uint32_t*)&sBL[bn * 40 + ac];
                bL[1] = *(uint32_t*)&sBL[bn * 40 + ac + 8];
                #pragma unroll
                for (int mt = 0; mt < 2; mt++) {
                    mma16816(acc[mt][nt], aH[mt], bH);
                    mma16816(acc[mt][nt], aH[mt], bL);
                    mma16816(acc[mt][nt], aL[mt], bH);
                }
            }
        }
    }

    #pragma unroll
    for (int mt = 0; mt < 2; mt++) {
        #pragma unroll
        for (int nt = 0; nt < 8; nt++) {
            int m = m0 + warpM * 32 + mt * 16 + r;
            int n = n0 + warpN * 64 + nt * 8 + cc;
            unsigned short h0, l0, h1, l1, h2, l2, h3, l3;
            bsplit(acc[mt][nt][0], h0, l0); bsplit(acc[mt][nt][1], h1, l1);
            bsplit(acc[mt][nt][2], h2, l2); bsplit(acc[mt][nt][3], h3, l3);
            *(uint32_t*)&CH[(size_t)m * 256 + n] = pack2(h0, h1);
            *(uint32_t*)&CL[(size_t)m * 256 + n] = pack2(l0, l1);
            *(uint32_t*)&CH[(size_t)(m + 8) * 256 + n] = pack2(h2, h3);
            *(uint32_t*)&CL[(size_t)(m + 8) * 256 + n] = pack2(l2, l3);
        }
    }
}

// ---------------------------------------------------------------------------
// GEMM3 fused with combine: out = tanh([ctx | dec] @ W_fin). ctx merged
// in-register from fp32 split-KV partials (active slices only); combine
// weights computed in the prologue from g_pm/g_pl (no separate kernel).
// ---------------------------------------------------------------------------
__global__ __launch_bounds__(256, 2)
void mma_gemm3_fused(const __nv_bfloat16* __restrict__ decH,
                     const __nv_bfloat16* __restrict__ decL,
                     const __nv_bfloat16* __restrict__ BTH,
                     const __nv_bfloat16* __restrict__ BTL,
                     float* __restrict__ out)
{
    extern __shared__ char dyn[];
    __shared__ float wsm[128][4];
    uint32_t base = smem_u32(dyn);

    int tid = threadIdx.x, lane = tid & 31, wid = tid >> 5;
    int warpM = wid & 3, warpN = wid >> 2;
    int m0 = blockIdx.y * 128, n0 = blockIdx.x * 128;
    int r = lane >> 2, cc = (lane & 3) * 2;
    int nsl = min(NSLICE, (g_lengths[m0 >> 10] + SLICE_S - 1) / SLICE_S);

    // combine weights for this CTA's 128 rows
    if (tid < 128) {
        int m = m0 + tid;
        float mv[4], lv[4];
        float M = -1e30f;
        for (int s = 0; s < nsl; s++) {
            mv[s] = g_pm[s * MTOT + m];
            lv[s] = g_pl[s * MTOT + m];
            M = fmaxf(M, mv[s]);
        }
        float L = 0.f, ws[4];
        for (int s = 0; s < nsl; s++) {
            float e = __expf(mv[s] - M);
            ws[s] = e;
            L += e * lv[s];
        }
        float inv = 1.0f / L;
        #pragma unroll
        for (int s = 0; s < 4; s++)
            wsm[tid][s] = (s < nsl) ? ws[s] * inv : 0.f;
    }
    __syncthreads();

    float wreg[2][4];
    #pragma unroll
    for (int u = 0; u < 2; u++) {
        int rr = (tid + u * 256) >> 2;
        #pragma unroll
        for (int s = 0; s < 4; s++)
            wreg[u][s] = wsm[rr][s];
    }

    float acc[2][8][4];
    #pragma unroll
    for (int i = 0; i < 2; i++)
        #pragma unroll
        for (int j = 0; j < 8; j++)
            #pragma unroll
            for (int q = 0; q < 4; q++) acc[i][j][q] = 0.f;

    auto stage = [&](int ch, int buf) {
        uint32_t bb = base + buf * PG_BUF;
        int kc = ch * 32;
        #pragma unroll
        for (int u = 0; u < 2; u++) {
            int f = tid + u * 256;
            int rr = f >> 2, c = f & 3;
            uint32_t doff = rr * 80 + c * 16;
            size_t gb = (size_t)(n0 + rr) * 512 + kc + c * 8;
            cp16(bb + PG_BH + doff, BTH + gb);
            cp16(bb + PG_BL + doff, BTL + gb);
        }
        if (ch >= 8) {
            int kcol = kc - 256;
            #pragma unroll
            for (int u = 0; u < 2; u++) {
                int f = tid + u * 256;
                int rr = f >> 2, c = f & 3;
                uint32_t doff = rr * 80 + c * 16;
                size_t ga = (size_t)(m0 + rr) * 256 + kcol + c * 8;
                cp16(bb + PG_AH + doff, decH + ga);
                cp16(bb + PG_AL + doff, decL + ga);
            }
        } else {
            __nv_bfloat16* sAH = (__nv_bfloat16*)(dyn + buf * PG_BUF + PG_AH);
            __nv_bfloat16* sAL = (__nv_bfloat16*)(dyn + buf * PG_BUF + PG_AL);
            #pragma unroll
            for (int u = 0; u < 2; u++) {
                int f = tid + u * 256;
                int rr = f >> 2, c8 = f & 3;
                int m = m0 + rr;
                float v[8] = {0, 0, 0, 0, 0, 0, 0, 0};
                for (int s = 0; s < nsl; s++) {
                    float w = wreg[u][s];
                    const float* p =
                        &g_pctx[((size_t)s * MTOT + m) * 256 + kc + c8 * 8];
                    float4 a = *(const float4*)p;
                    float4 bq = *(const float4*)(p + 4);
                    v[0] += w * a.x;  v[1] += w * a.y;
                    v[2] += w * a.z;  v[3] += w * a.w;
                    v[4] += w * bq.x; v[5] += w * bq.y;
                    v[6] += w * bq.z; v[7] += w * bq.w;
                }
                ushort4 hv1, lv1, hv2, lv2;
                bsplit(v[0], hv1.x, lv1.x); bsplit(v[1], hv1.y, lv1.y);
                bsplit(v[2], hv1.z, lv1.z); bsplit(v[3], hv1.w, lv1.w);
                bsplit(v[4], hv2.x, lv2.x); bsplit(v[5], hv2.y, lv2.y);
                bsplit(v[6], hv2.z, lv2.z); bsplit(v[7], hv2.w, lv2.w);
                *(ushort4*)&sAH[rr * 40 + c8 * 8] = hv1;
                *(ushort4*)&sAH[rr * 40 + c8 * 8 + 4] = hv2;
                *(ushort4*)&sAL[rr * 40 + c8 * 8] = lv1;
                *(ushort4*)&sAL[rr * 40 + c8 * 8 + 4] = lv2;
            }
        }
    };

    stage(0, 0);
    CP_COMMIT();

    for (int ch = 0; ch < 16; ch++) {
        CP_WAIT(0);
        __syncthreads();
        if (ch < 15) {
            stage(ch + 1, (ch + 1) & 1);
            CP_COMMIT();
        }
        const __nv_bfloat16* sAH =
            (const __nv_bfloat16*)(dyn + (ch & 1) * PG_BUF + PG_AH);
        const __nv_bfloat16* sAL =
            (const __nv_bfloat16*)(dyn + (ch & 1) * PG_BUF + PG_AL);
        const __nv_bfloat16* sBH =
            (const __nv_bfloat16*)(dyn + (ch & 1) * PG_BUF + PG_BH);
        const __nv_bfloat16* sBL =
            (const __nv_bfloat16*)(dyn + (ch & 1) * PG_BUF + PG_BL);

        #pragma unroll
        for (int ks = 0; ks < 2; ks++) {
            int ac = ks * 16 + cc;
            uint32_t aH[2][4], aL[2][4];
            #pragma unroll
            for (int mt = 0; mt < 2; mt++) {
                int ar = warpM * 32 + mt * 16 + r;
                aH[mt][0] = *(uint32_t*)&sAH[ar * 40 + ac];
                aH[mt][1] = *(uint32_t*)&sAH[(ar + 8) * 40 + ac];
                aH[mt][2] = *(uint32_t*)&sAH[ar * 40 + ac + 8];
                aH[mt][3] = *(uint32_t*)&sAH[(ar + 8) * 40 + ac + 8];
                aL[mt][0] = *(uint32_t*)&sAL[ar * 40 + ac];
                aL[mt][1] = *(uint32_t*)&sAL[(ar + 8) * 40 + ac];
                aL[mt][2] = *(uint32_t*)&sAL[ar * 40 + ac + 8];
                aL[mt][3] = *(uint32_t*)&sAL[(ar + 8) * 40 + ac + 8];
            }
            #pragma unroll
            for (int nt = 0; nt < 8; nt++) {
                int bn = warpN * 64 + nt * 8 + r;
                uint32_t bH[2], bL[2];
                bH[0] = *(uint32_t*)&sBH[bn * 40 + ac];
                bH[1] = *(uint32_t*)&sBH[bn * 40 + ac + 8];
                bL[0] = *(uint32_t*)&sBL[bn * 40 + ac];
                bL[1] = *(uint32_t*)&sBL[bn * 40 + ac + 8];
                #pragma unroll
                for (int mt = 0; mt < 2; mt++) {
                    mma16816(acc[mt][nt], aH[mt], bH);
                    mma16816(acc[mt][nt], aH[mt], bL);
                    mma16816(acc[mt][nt], aL[mt], bH);
                }
            }
        }
    }

    #pragma unroll
    for (int mt = 0; mt < 2; mt++) {
        #pragma unroll
        for (int nt = 0; nt < 8; nt++) {
            int m = m0 + warpM * 32 + mt * 16 + r;
            int n = n0 + warpN * 64 + nt * 8 + cc;
            float2 v0 = make_float2(tanhf(acc[mt][nt][0]), tanhf(acc[mt][nt][1]));
            float2 v1 = make_float2(tanhf(acc[mt][nt][2]), tanhf(acc[mt][nt][3]));
            *(float2*)&out[(size_t)m * 256 + n] = v0;
            *(float2*)&out[(size_t)(m + 8) * 256 + n] = v1;
        }
    }
}

// ---------------------------------------------------------------------------
// Fused flash attention (round-8 committed version, fp32 partial epilogue)
// ---------------------------------------------------------------------------
#define O_AH0 0
#define O_AL0 9216
#define O_AH1 18432
#define O_AL1 27648
#define O_E   36864
#define O_PMAX 110592
#define O_PSUM 111104
#define A_TOTAL 111616

__device__ __forceinline__ void stage_chunk(uint32_t base, int abuf, int ch,
                                            size_t dpBase, size_t encBase,
                                            int s0, int tid)
{
    uint32_t ah = base + (abuf ? O_AH1 : O_AH0);
    uint32_t al = ah + 9216;
    uint32_t eh = base + O_E + ch * 18432;
    uint32_t el = eh + 9216;
    int kc = ch * 64;
    #pragma unroll
    for (int u = 0; u < 2; u++) {
        int f = tid + u * 256;
        int rr = f >> 3, c = f & 7;
        uint32_t doff = rr * 144 + c * 16;
        size_t ga = dpBase + (size_t)rr * 256 + kc + c * 8;
        size_t ge = encBase + (size_t)(s0 + rr) * 256 + kc + c * 8;
        cp16(ah + doff, g_dpH + ga);
        cp16(al + doff, g_dpL + ga);
        cp16(eh + doff, g_encH + ge);
        cp16(el + doff, g_encL + ge);
    }
}

__global__ __launch_bounds__(256, 2)
void attn_kernel()
{
    extern __shared__ char dyn[];
    uint32_t base = smem_u32(dyn);
    float* sPmax = (float*)(dyn + O_PMAX);
    float* sPsum = (float*)(dyn + O_PSUM);
    __nv_bfloat16* pH = (__nv_bfloat16*)(dyn + O_AH1);
    __nv_bfloat16* pL = (__nv_bfloat16*)(dyn + O_AL1);

    int tid = threadIdx.x, lane = tid & 31, wid = tid >> 5;
    int warpT = wid & 3;
    int warpS = wid >> 2;
    int r = lane >> 2, cc = (lane & 3) * 2;
    int b = blockIdx.y;
    int t0 = blockIdx.x * 64;
    int slice = blockIdx.z;
    int len = g_lengths[b];

    int sbeg = slice * SLICE_S;
    if (sbeg >= len) return;
    int send = min(sbeg + SLICE_S, len);

    size_t dpBase = ((size_t)b * Tt + t0) * 256;
    size_t encBase = (size_t)b * Ss * 256;

    int row0 = warpT * 16 + r;
    int row1 = row0 + 8;
    float mreg0 = -1e30f, mreg1 = -1e30f;
    float lreg0 = 0.f, lreg1 = 0.f;

    float ctx[4][4][4];
    #pragma unroll
    for (int i = 0; i < 4; i++)
        #pragma unroll
        for (int j = 0; j < 4; j++)
            #pragma unroll
            for (int q = 0; q < 4; q++) ctx[i][j][q] = 0.f;

    stage_chunk(base, 0, 0, dpBase, encBase, sbeg, tid);
    CP_COMMIT();

    for (int s0 = sbeg; s0 < send; s0 += 64) {
        bool have_next = (s0 + 64 < send);

        float sacc[4][4];
        #pragma unroll
        for (int j = 0; j < 4; j++)
            #pragma unroll
            for (int q = 0; q < 4; q++) sacc[j][q] = 0.f;

        #pragma unroll
        for (int kch = 0; kch < 4; kch++) {
            if (kch < 3) {
                stage_chunk(base, (kch + 1) & 1, kch + 1, dpBase, encBase,
                            s0, tid);
                CP_COMMIT();
                CP_WAIT(1);
            } else {
                CP_WAIT(0);
            }
            __syncthreads();

            const __nv_bfloat16* sAH =
                (const __nv_bfloat16*)(dyn + ((kch & 1) ? O_AH1 : O_AH0));
            const __nv_bfloat16* sAL = sAH + 4608;
            const __nv_bfloat16* sBH =
                (const __nv_bfloat16*)(dyn + O_E + kch * 18432);
            const __nv_bfloat16* sBL = sBH + 4608;

            #pragma unroll
            for (int ks = 0; ks < 4; ks++) {
                int ac = ks * 16 + cc;
                int ar = warpT * 16 + r;
                uint32_t aH[4], aL[4];
                aH[0] = *(uint32_t*)&sAH[ar * 72 + ac];
                aH[1] = *(uint32_t*)&sAH[(ar + 8) * 72 + ac];
                aH[2] = *(uint32_t*)&sAH[ar * 72 + ac + 8];
                aH[3] = *(uint32_t*)&sAH[(ar + 8) * 72 + ac + 8];
                aL[0] = *(uint32_t*)&sAL[ar * 72 + ac];
                aL[1] = *(uint32_t*)&sAL[(ar + 8) * 72 + ac];
                aL[2] = *(uint32_t*)&sAL[ar * 72 + ac + 8];
                aL[3] = *(uint32_t*)&sAL[(ar + 8) * 72 + ac + 8];
                #pragma unroll
                for (int nt = 0; nt < 4; nt++) {
                    int bn = warpS * 32 + nt * 8 + r;
                    uint32_t bH[2], bL[2];
                    bH[0] = *(uint32_t*)&sBH[bn * 72 + ac];
                    bH[1] = *(uint32_t*)&sBH[bn * 72 + ac + 8];
                    bL[0] = *(uint32_t*)&sBL[bn * 72 + ac];
                    bL[1] = *(uint32_t*)&sBL[bn * 72 + ac + 8];
                    mma16816(sacc[nt], aH, bH);
                    mma16816(sacc[nt], aH, bL);
                    mma16816(sacc[nt], aL, bH);
                }
            }
            __syncthreads();
        }

        // register softmax
        float rm0 = -1e30f, rm1 = -1e30f;
        #pragma unroll
        for (int nt = 0; nt < 4; nt++) {
            int cg = s0 + warpS * 32 + nt * 8 + cc;
            if (cg >= len)     { sacc[nt][0] = -1e30f; sacc[nt][2] = -1e30f; }
            if (cg + 1 >= len) { sacc[nt][1] = -1e30f; sacc[nt][3] = -1e30f; }
            rm0 = fmaxf(rm0, fmaxf(sacc[nt][0], sacc[nt][1]));
            rm1 = fmaxf(rm1, fmaxf(sacc[nt][2], sacc[nt][3]));
        }
        rm0 = fmaxf(rm0, __shfl_xor_sync(0xffffffffu, rm0, 1));
        rm0 = fmaxf(rm0, __shfl_xor_sync(0xffffffffu, rm0, 2));
        rm1 = fmaxf(rm1, __shfl_xor_sync(0xffffffffu, rm1, 1));
        rm1 = fmaxf(rm1, __shfl_xor_sync(0xffffffffu, rm1, 2));
        if ((lane & 3) == 0) {
            sPmax[row0 * 2 + warpS] = rm0;
            sPmax[row1 * 2 + warpS] = rm1;
        }
        __syncthreads();

        float mN0 = fmaxf(mreg0, fmaxf(sPmax[row0 * 2], sPmax[row0 * 2 + 1]));
        float mN1 = fmaxf(mreg1, fmaxf(sPmax[row1 * 2], sPmax[row1 * 2 + 1]));
        float scl0 = __expf(mreg0 - mN0);
        float scl1 = __expf(mreg1 - mN1);
        mreg0 = mN0; mreg1 = mN1;

        float sum0 = 0.f, sum1 = 0.f;
        #pragma unroll
        for (int nt = 0; nt < 4; nt++) {
            sacc[nt][0] = __expf(sacc[nt][0] - mN0);
            sacc[nt][1] = __expf(sacc[nt][1] - mN0);
            sacc[nt][2] = __expf(sacc[nt][2] - mN1);
            sacc[nt][3] = __expf(sacc[nt][3] - mN1);
            sum0 += sacc[nt][0] + sacc[nt][1];
            sum1 += sacc[nt][2] + sacc[nt][3];
        }
        sum0 += __shfl_xor_sync(0xffffffffu, sum0, 1);
        sum0 += __shfl_xor_sync(0xffffffffu, sum0, 2);
        sum1 += __shfl_xor_sync(0xffffffffu, sum1, 1);
        sum1 += __shfl_xor_sync(0xffffffffu, sum1, 2);
        if ((lane & 3) == 0) {
            sPsum[row0 * 2 + warpS] = sum0;
            sPsum[row1 * 2 + warpS] = sum1;
        }
        #pragma unroll
        for (int nt = 0; nt < 4; nt++) {
            int colb = warpS * 32 + nt * 8 + cc;
            unsigned short h0, l0, h1, l1, h2, l2, h3, l3;
            bsplit(sacc[nt][0], h0, l0); bsplit(sacc[nt][1], h1, l1);
            bsplit(sacc[nt][2], h2, l2); bsplit(sacc[nt][3], h3, l3);
            *(uint32_t*)&pH[row0 * 72 + colb] = pack2(h0, h1);
            *(uint32_t*)&pL[row0 * 72 + colb] = pack2(l0, l1);
            *(uint32_t*)&pH[row1 * 72 + colb] = pack2(h2, h3);
            *(uint32_t*)&pL[row1 * 72 + colb] = pack2(l2, l3);
        }
        __syncthreads();

        lreg0 = lreg0 * scl0 + sPsum[row0 * 2] + sPsum[row0 * 2 + 1];
        lreg1 = lreg1 * scl1 + sPsum[row1 * 2] + sPsum[row1 * 2 + 1];
        #pragma unroll
        for (int i = 0; i < 4; i++)
            #pragma unroll
            for (int j = 0; j < 4; j++) {
                ctx[i][j][0] *= scl0; ctx[i][j][1] *= scl0;
                ctx[i][j][2] *= scl1; ctx[i][j][3] *= scl1;
            }

        // context GEMM (reuse E chunks)
        #pragma unroll
        for (int ch = 0; ch < 4; ch++) {
            uint32_t ehb = base + O_E + ch * 18432;
            uint32_t elb = ehb + 9216;
            #pragma unroll
            for (int ks = 0; ks < 4; ks++) {
                int ac = ks * 16 + cc;
                int ar = warpT * 16 + r;
                uint32_t aH[4], aL[4];
                aH[0] = *(uint32_t*)&pH[ar * 72 + ac];
                aH[1] = *(uint32_t*)&pH[(ar + 8) * 72 + ac];
                aH[2] = *(uint32_t*)&pH[ar * 72 + ac + 8];
                aH[3] = *(uint32_t*)&pH[(ar + 8) * 72 + ac + 8];
                aL[0] = *(uint32_t*)&pL[ar * 72 + ac];
                aL[1] = *(uint32_t*)&pL[(ar + 8) * 72 + ac];
                aL[2] = *(uint32_t*)&pL[ar * 72 + ac + 8];
                aL[3] = *(uint32_t*)&pL[(ar + 8) * 72 + ac + 8];
                uint32_t lrow = (uint32_t)(ks * 16 + (lane & 15));
                uint32_t lcol0 = (uint32_t)(warpS * 32 + ((lane >> 4) << 3));
                #pragma unroll
                for (int pair = 0; pair < 2; pair++) {
                    uint32_t off = (lrow * 72 + lcol0 + pair * 16) * 2;
                    uint32_t bh0, bh1, bh2, bh3, bl0, bl1, bl2, bl3;
                    ldsm_x4_t(bh0, bh1, bh2, bh3, ehb + off);
                    ldsm_x4_t(bl0, bl1, bl2, bl3, elb + off);
                    uint32_t bH0[2] = {bh0, bh1}, bH1[2] = {bh2, bh3};
                    uint32_t bL0[2] = {bl0, bl1}, bL1[2] = {bl2, bl3};
                    int nt = pair * 2;
                    mma16816(ctx[ch][nt], aH, bH0);
                    mma16816(ctx[ch][nt], aH, bL0);
                    mma16816(ctx[ch][nt], aL, bH0);
                    mma16816(ctx[ch][nt + 1], aH, bH1);
                    mma16816(ctx[ch][nt + 1], aH, bL1);
                    mma16816(ctx[ch][nt + 1], aL, bH1);
                }
            }
            if (ch == 0) {
                __syncthreads();
                if (have_next) {
                    stage_chunk(base, 0, 0, dpBase, encBase, s0 + 64, tid);
                    CP_COMMIT();
                }
            }
        }
        __syncthreads();
    }

    // write partials (fp32)
    size_t pmBase = (((size_t)slice * Bb + b) * Tt) + t0;
    if (warpS == 0 && (lane & 3) == 0) {
        g_pm[pmBase + row0] = mreg0;
        g_pm[pmBase + row1] = mreg1;
        g_pl[pmBase + row0] = lreg0;
        g_pl[pmBase + row1] = lreg1;
    }
    int t = t0 + row0;
    size_t obase = (((size_t)slice * Bb + b) * Tt + t) * 256;
    #pragma unroll
    for (int ch = 0; ch < 4; ch++) {
        #pragma unroll
        for (int nt = 0; nt < 4; nt++) {
            int e = ch * 64 + warpS * 32 + nt * 8 + cc;
            *(float2*)&g_pctx[obase + e] =
                make_float2(ctx[ch][nt][0], ctx[ch][nt][1]);
            *(float2*)&g_pctx[obase + 8 * 256 + e] =
                make_float2(ctx[ch][nt][2], ctx[ch][nt][3]);
        }
    }
}

// ---------------------------------------------------------------------------
extern "C" void kernel_launch(void* const* d_in, const int* in_sizes, int n_in,
                              void* d_out, int out_size)
{
    (void)in_sizes; (void)n_in; (void)out_size;
    const float* enc = (const float*)d_in[0];
    const float* dec = (const float*)d_in[1];
    const unsigned char* mask = (const unsigned char*)d_in[2];
    const float* W_enc = (const float*)d_in[3];
    const float* W_fin = (const float*)d_in[4];
    float* out = (float*)d_out;

    void *pDecH, *pDecL, *pDpH, *pDpL, *pWeH, *pWeL, *pWfH, *pWfL;
    cudaGetSymbolAddress(&pDecH, g_decH);
    cudaGetSymbolAddress(&pDecL, g_decL);
    cudaGetSymbolAddress(&pDpH, g_dpH);
    cudaGetSymbolAddress(&pDpL, g_dpL);
    cudaGetSymbolAddress(&pWeH, g_WencH);
    cudaGetSymbolAddress(&pWeL, g_WencL);
    cudaGetSymbolAddress(&pWfH, g_WfinTH);
    cudaGetSymbolAddress(&pWfL, g_WfinTL);

    cudaFuncSetAttribute((const void*)mma_gemm1_kernel,
                         cudaFuncAttributeMaxDynamicSharedMemorySize, PG_TOTAL);
    cudaFuncSetAttribute((const void*)mma_gemm3_fused,
                         cudaFuncAttributeMaxDynamicSharedMemorySize, PG_TOTAL);
    cudaFuncSetAttribute((const void*)attn_kernel,
                         cudaFuncAttributeMaxDynamicSharedMemorySize, A_TOTAL);

    detect_lengths_kernel<<<1, 256>>>(mask);
    prep_convert_kernel<<<1024, 256>>>(enc, dec, W_enc, W_fin);

    // GEMM1': decproj = dec @ W_enc^T
    dim3 g1(2, 128);
    mma_gemm1_kernel<<<g1, 256, PG_TOTAL>>>(
        (const __nv_bfloat16*)pDecH, (const __nv_bfloat16*)pDecL,
        (const __nv_bfloat16*)pWeH, (const __nv_bfloat16*)pWeL,
        (__nv_bfloat16*)pDpH, (__nv_bfloat16*)pDpL);

    dim3 g2(Tt / 64, Bb, NSLICE);
    attn_kernel<<<g2, 256, A_TOTAL>>>();

    // GEMM3 fused with combine (weights computed in-kernel)
    dim3 g3(2, 128);
    mma_gemm3_fused<<<g3, 256, PG_TOTAL>>>(
        (const __nv_bfloat16*)pDecH, (const __nv_bfloat16*)pDecL,
        (const __nv_bfloat16*)pWfH, (const __nv_bfloat16*)pWfL,
        out);
}

// round 11
// speedup vs baseline: 1.4926x; 1.4926x over previous
#include <cuda_runtime.h>
#include <cuda_bf16.h>
#include <math.h>
#include <stdint.h>

#define Bb 16
#define Ss 2048
#define Tt 1024
#define Ee 256
#define Dd 256
#define NSLICE 4
#define SLICE_S 512
#define MTOT (Bb * Tt)   // 16384

// ---------------------------------------------------------------------------
// Scratch (allocation-free device globals), bf16 hi/lo split representations.
// ---------------------------------------------------------------------------
__device__ __nv_bfloat16 g_encH[Bb * Ss * Ee];
__device__ __nv_bfloat16 g_encL[Bb * Ss * Ee];
__device__ __nv_bfloat16 g_decH[Bb * Tt * Dd];
__device__ __nv_bfloat16 g_decL[Bb * Tt * Dd];
__device__ __nv_bfloat16 g_dpH[Bb * Tt * Ee];     // decproj hi
__device__ __nv_bfloat16 g_dpL[Bb * Tt * Ee];     // decproj lo
__device__ __nv_bfloat16 g_WencH[Ee * Dd];        // W_enc native [e][d]
__device__ __nv_bfloat16 g_WencL[Ee * Dd];
__device__ __nv_bfloat16 g_WfinTH[Dd * (Ee + Dd)];
__device__ __nv_bfloat16 g_WfinTL[Dd * (Ee + Dd)];
__device__ int g_lengths[Bb];
__device__ float g_pctx[NSLICE * MTOT * Ee];      // fp32 split-KV partials
__device__ float g_pm[NSLICE * MTOT];
__device__ float g_pl[NSLICE * MTOT];

// ---------------------------------------------------------------------------
// Helpers
// ---------------------------------------------------------------------------
__device__ __forceinline__ uint32_t smem_u32(const void* p) {
    uint32_t a;
    asm("{ .reg .u64 t; cvta.to.shared.u64 t, %1; cvt.u32.u64 %0, t; }"
        : "=r"(a) : "l"(p));
    return a;
}

__device__ __forceinline__ void mma16816(float* d, const uint32_t* a,
                                         const uint32_t* b) {
    asm volatile(
        "mma.sync.aligned.m16n8k16.row.col.f32.bf16.bf16.f32 "
        "{%0,%1,%2,%3}, {%4,%5,%6,%7}, {%8,%9}, {%0,%1,%2,%3};"
        : "+f"(d[0]), "+f"(d[1]), "+f"(d[2]), "+f"(d[3])
        : "r"(a[0]), "r"(a[1]), "r"(a[2]), "r"(a[3]), "r"(b[0]), "r"(b[1]));
}

__device__ __forceinline__ void ldsm_x4_t(uint32_t& r0, uint32_t& r1,
                                          uint32_t& r2, uint32_t& r3,
                                          uint32_t addr) {
    asm volatile("ldmatrix.sync.aligned.m8n8.x4.trans.shared.b16 "
                 "{%0,%1,%2,%3}, [%4];"
                 : "=r"(r0), "=r"(r1), "=r"(r2), "=r"(r3) : "r"(addr));
}

__device__ __forceinline__ void cp16(uint32_t dst, const void* src) {
    asm volatile("cp.async.cg.shared.global [%0], [%1], 16;"
                 :: "r"(dst), "l"(src));
}
#define CP_COMMIT() asm volatile("cp.async.commit_group;")
#define CP_WAIT(N)  asm volatile("cp.async.wait_group %0;" :: "n"(N))

__device__ __forceinline__ void bsplit(float x, unsigned short& h,
                                       unsigned short& l) {
    __nv_bfloat16 hb = __float2bfloat16(x);
    __nv_bfloat16 lb = __float2bfloat16(x - __bfloat162float(hb));
    h = *(unsigned short*)&hb;
    l = *(unsigned short*)&lb;
}

__device__ __forceinline__ uint32_t pack2(unsigned short a, unsigned short b) {
    return (uint32_t)a | ((uint32_t)b << 16);
}

// ---------------------------------------------------------------------------
// Mask prologue (handles uint8 or int32 bool encodings)
// ---------------------------------------------------------------------------
__global__ void detect_lengths_kernel(const unsigned char* __restrict__ mask)
{
    __shared__ int s_flag;
    __shared__ int s_cnt[Bb];
    int tid = threadIdx.x;
    if (tid == 0) s_flag = 0;
    if (tid < Bb) s_cnt[tid] = 0;
    __syncthreads();

    int local = 0;
    for (int i = tid; i < Bb * Ss; i += 256)
        if ((i & 3) != 0 && mask[i] != 0) local = 1;
    if (local) atomicOr(&s_flag, 1);
    __syncthreads();

    bool isU8 = (s_flag != 0);
    int row = tid >> 4, part = tid & 15;
    int cnt = 0;
    if (isU8) {
        const unsigned char* p = mask + row * Ss + part * 128;
        #pragma unroll 4
        for (int e = 0; e < 128; e++) cnt += (p[e] != 0);
    } else {
        const int* p = ((const int*)mask) + row * Ss + part * 128;
        #pragma unroll 4
        for (int e = 0; e < 128; e++) cnt += (p[e] != 0);
    }
    atomicAdd(&s_cnt[row], cnt);
    __syncthreads();
    if (tid < Bb) g_lengths[tid] = s_cnt[tid];
}

// ---------------------------------------------------------------------------
// Prep: fp32 -> bf16 hi/lo for enc, dec; W_enc split; W_fin transposed+split.
// ---------------------------------------------------------------------------
__global__ void prep_convert_kernel(const float* __restrict__ enc,
                                    const float* __restrict__ dec,
                                    const float* __restrict__ Wenc,
                                    const float* __restrict__ Wfin)
{
    int tid = blockIdx.x * blockDim.x + threadIdx.x;
    int stride = gridDim.x * blockDim.x;

    const int NE4 = (Bb * Ss * Ee) / 4;
    for (int i = tid; i < NE4; i += stride) {
        float4 v = ((const float4*)enc)[i];
        ushort4 hv, lv;
        bsplit(v.x, hv.x, lv.x); bsplit(v.y, hv.y, lv.y);
        bsplit(v.z, hv.z, lv.z); bsplit(v.w, hv.w, lv.w);
        ((ushort4*)g_encH)[i] = hv;
        ((ushort4*)g_encL)[i] = lv;
    }
    const int ND4 = (Bb * Tt * Dd) / 4;
    for (int i = tid; i < ND4; i += stride) {
        float4 v = ((const float4*)dec)[i];
        ushort4 hv, lv;
        bsplit(v.x, hv.x, lv.x); bsplit(v.y, hv.y, lv.y);
        bsplit(v.z, hv.z, lv.z); bsplit(v.w, hv.w, lv.w);
        ((ushort4*)g_decH)[i] = hv;
        ((ushort4*)g_decL)[i] = lv;
    }
    for (int i = tid; i < 256 * 256; i += stride) {
        unsigned short h, l;
        bsplit(Wenc[i], h, l);
        *(unsigned short*)&g_WencH[i] = h;
        *(unsigned short*)&g_WencL[i] = l;
    }
    for (int i = tid; i < 256 * 512; i += stride) {
        int d = i >> 9, f = i & 511;
        unsigned short h, l;
        bsplit(Wfin[f * 256 + d], h, l);
        *(unsigned short*)&g_WfinTH[i] = h;
        *(unsigned short*)&g_WfinTL[i] = l;
    }
}

// ---------------------------------------------------------------------------
// Pipelined GEMM smem: 32-wide k-chunks, stride 40 shorts (80 B) per row,
// double-buffered. Buffer = 4 matrices (Ah,Al,Bh,Bl) x 128 rows x 80 B.
// ---------------------------------------------------------------------------
#define PG_MAT   10240          // 128 * 80
#define PG_BUF   (4 * PG_MAT)   // 40960
#define PG_TOTAL (2 * PG_BUF)   // 81920
#define PG_AH 0
#define PG_AL PG_MAT
#define PG_BH (2 * PG_MAT)
#define PG_BL (3 * PG_MAT)

// ---------------------------------------------------------------------------
// GEMM1' (decproj = dec @ W_enc^T), K=256, 8 chunks, cp.async pipelined.
// ---------------------------------------------------------------------------
__global__ __launch_bounds__(256, 2)
void mma_gemm1_kernel(const __nv_bfloat16* __restrict__ A1H,
                      const __nv_bfloat16* __restrict__ A1L,
                      const __nv_bfloat16* __restrict__ BTH,
                      const __nv_bfloat16* __restrict__ BTL,
                      __nv_bfloat16* __restrict__ CH,
                      __nv_bfloat16* __restrict__ CL)
{
    extern __shared__ char dyn[];
    uint32_t base = smem_u32(dyn);

    int tid = threadIdx.x, lane = tid & 31, wid = tid >> 5;
    int warpM = wid & 3, warpN = wid >> 2;
    int m0 = blockIdx.y * 128, n0 = blockIdx.x * 128;
    int r = lane >> 2, cc = (lane & 3) * 2;

    float acc[2][8][4];
    #pragma unroll
    for (int i = 0; i < 2; i++)
        #pragma unroll
        for (int j = 0; j < 8; j++)
            #pragma unroll
            for (int q = 0; q < 4; q++) acc[i][j][q] = 0.f;

    auto stage = [&](int ch, int buf) {
        uint32_t bb = base + buf * PG_BUF;
        int kc = ch * 32;
        #pragma unroll
        for (int u = 0; u < 2; u++) {
            int f = tid + u * 256;
            int rr = f >> 2, c = f & 3;
            uint32_t doff = rr * 80 + c * 16;
            size_t ga = (size_t)(m0 + rr) * 256 + kc + c * 8;
            size_t gb = (size_t)(n0 + rr) * 256 + kc + c * 8;
            cp16(bb + PG_AH + doff, A1H + ga);
            cp16(bb + PG_AL + doff, A1L + ga);
            cp16(bb + PG_BH + doff, BTH + gb);
            cp16(bb + PG_BL + doff, BTL + gb);
        }
    };

    stage(0, 0);
    CP_COMMIT();

    for (int ch = 0; ch < 8; ch++) {
        CP_WAIT(0);
        __syncthreads();
        if (ch < 7) {
            stage(ch + 1, (ch + 1) & 1);
            CP_COMMIT();
        }
        const __nv_bfloat16* sAH =
            (const __nv_bfloat16*)(dyn + (ch & 1) * PG_BUF + PG_AH);
        const __nv_bfloat16* sAL =
            (const __nv_bfloat16*)(dyn + (ch & 1) * PG_BUF + PG_AL);
        const __nv_bfloat16* sBH =
            (const __nv_bfloat16*)(dyn + (ch & 1) * PG_BUF + PG_BH);
        const __nv_bfloat16* sBL =
            (const __nv_bfloat16*)(dyn + (ch & 1) * PG_BUF + PG_BL);

        #pragma unroll
        for (int ks = 0; ks < 2; ks++) {
            int ac = ks * 16 + cc;
            uint32_t aH[2][4], aL[2][4];
            #pragma unroll
            for (int mt = 0; mt < 2; mt++) {
                int ar = warpM * 32 + mt * 16 + r;
                aH[mt][0] = *(uint32_t*)&sAH[ar * 40 + ac];
                aH[mt][1] = *(uint32_t*)&sAH[(ar + 8) * 40 + ac];
                aH[mt][2] = *(uint32_t*)&sAH[ar * 40 + ac + 8];
                aH[mt][3] = *(uint32_t*)&sAH[(ar + 8) * 40 + ac + 8];
                aL[mt][0] = *(uint32_t*)&sAL[ar * 40 + ac];
                aL[mt][1] = *(uint32_t*)&sAL[(ar + 8) * 40 + ac];
                aL[mt][2] = *(uint32_t*)&sAL[ar * 40 + ac + 8];
                aL[mt][3] = *(uint32_t*)&sAL[(ar + 8) * 40 + ac + 8];
            }
            #pragma unroll
            for (int nt = 0; nt < 8; nt++) {
                int bn = warpN * 64 + nt * 8 + r;
                uint32_t bH[2], bL[2];
                bH[0] = *(uint32_t*)&sBH[bn * 40 + ac];
                bH[1] = *(uint32_t*)&sBH[bn * 40 + ac + 8];
                bL[0] = *(uint32_t*)&sBL[bn * 40 + ac];
                bL[1] = *(uint32_t*)&sBL[bn * 40 + ac + 8];
                #pragma unroll
                for (int mt = 0; mt < 2; mt++) {
                    mma16816(acc[mt][nt], aH[mt], bH);
                    mma16816(acc[mt][nt], aH[mt], bL);
                    mma16816(acc[mt][nt], aL[mt], bH);
                }
            }
        }
    }

    #pragma unroll
    for (int mt = 0; mt < 2; mt++) {
        #pragma unroll
        for (int nt = 0; nt < 8; nt++) {
            int m = m0 + warpM * 32 + mt * 16 + r;
            int n = n0 + warpN * 64 + nt * 8 + cc;
            unsigned short h0, l0, h1, l1, h2, l2, h3, l3;
            bsplit(acc[mt][nt][0], h0, l0); bsplit(acc[mt][nt][1], h1, l1);
            bsplit(acc[mt][nt][2], h2, l2); bsplit(acc[mt][nt][3], h3, l3);
            *(uint32_t*)&CH[(size_t)m * 256 + n] = pack2(h0, h1);
            *(uint32_t*)&CL[(size_t)m * 256 + n] = pack2(l0, l1);
            *(uint32_t*)&CH[(size_t)(m + 8) * 256 + n] = pack2(h2, h3);
            *(uint32_t*)&CL[(size_t)(m + 8) * 256 + n] = pack2(l2, l3);
        }
    }
}

// ---------------------------------------------------------------------------
// GEMM3 fused with combine: out = tanh([ctx | dec] @ W_fin). ctx merged
// in-register from fp32 split-KV partials (active slices only); combine
// weights computed in the prologue from g_pm/g_pl (no separate kernel).
// ---------------------------------------------------------------------------
__global__ __launch_bounds__(256, 2)
void mma_gemm3_fused(const __nv_bfloat16* __restrict__ decH,
                     const __nv_bfloat16* __restrict__ decL,
                     const __nv_bfloat16* __restrict__ BTH,
                     const __nv_bfloat16* __restrict__ BTL,
                     float* __restrict__ out)
{
    extern __shared__ char dyn[];
    __shared__ float wsm[128][4];
    uint32_t base = smem_u32(dyn);

    int tid = threadIdx.x, lane = tid & 31, wid = tid >> 5;
    int warpM = wid & 3, warpN = wid >> 2;
    int m0 = blockIdx.y * 128, n0 = blockIdx.x * 128;
    int r = lane >> 2, cc = (lane & 3) * 2;
    int nsl = min(NSLICE, (g_lengths[m0 >> 10] + SLICE_S - 1) / SLICE_S);

    // combine weights for this CTA's 128 rows
    if (tid < 128) {
        int m = m0 + tid;
        float mv[4], lv[4];
        float M = -1e30f;
        for (int s = 0; s < nsl; s++) {
            mv[s] = g_pm[s * MTOT + m];
            lv[s] = g_pl[s * MTOT + m];
            M = fmaxf(M, mv[s]);
        }
        float L = 0.f, ws[4];
        for (int s = 0; s < nsl; s++) {
            float e = __expf(mv[s] - M);
            ws[s] = e;
            L += e * lv[s];
        }
        float inv = 1.0f / L;
        #pragma unroll
        for (int s = 0; s < 4; s++)
            wsm[tid][s] = (s < nsl) ? ws[s] * inv : 0.f;
    }
    __syncthreads();

    float wreg[2][4];
    #pragma unroll
    for (int u = 0; u < 2; u++) {
        int rr = (tid + u * 256) >> 2;
        #pragma unroll
        for (int s = 0; s < 4; s++)
            wreg[u][s] = wsm[rr][s];
    }

    float acc[2][8][4];
    #pragma unroll
    for (int i = 0; i < 2; i++)
        #pragma unroll
        for (int j = 0; j < 8; j++)
            #pragma unroll
            for (int q = 0; q < 4; q++) acc[i][j][q] = 0.f;

    auto stage = [&](int ch, int buf) {
        uint32_t bb = base + buf * PG_BUF;
        int kc = ch * 32;
        #pragma unroll
        for (int u = 0; u < 2; u++) {
            int f = tid + u * 256;
            int rr = f >> 2, c = f & 3;
            uint32_t doff = rr * 80 + c * 16;
            size_t gb = (size_t)(n0 + rr) * 512 + kc + c * 8;
            cp16(bb + PG_BH + doff, BTH + gb);
            cp16(bb + PG_BL + doff, BTL + gb);
        }
        if (ch >= 8) {
            int kcol = kc - 256;
            #pragma unroll
            for (int u = 0; u < 2; u++) {
                int f = tid + u * 256;
                int rr = f >> 2, c = f & 3;
                uint32_t doff = rr * 80 + c * 16;
                size_t ga = (size_t)(m0 + rr) * 256 + kcol + c * 8;
                cp16(bb + PG_AH + doff, decH + ga);
                cp16(bb + PG_AL + doff, decL + ga);
            }
        } else {
            __nv_bfloat16* sAH = (__nv_bfloat16*)(dyn + buf * PG_BUF + PG_AH);
            __nv_bfloat16* sAL = (__nv_bfloat16*)(dyn + buf * PG_BUF + PG_AL);
            #pragma unroll
            for (int u = 0; u < 2; u++) {
                int f = tid + u * 256;
                int rr = f >> 2, c8 = f & 3;
                int m = m0 + rr;
                float v[8] = {0, 0, 0, 0, 0, 0, 0, 0};
                for (int s = 0; s < nsl; s++) {
                    float w = wreg[u][s];
                    const float* p =
                        &g_pctx[((size_t)s * MTOT + m) * 256 + kc + c8 * 8];
                    float4 a = *(const float4*)p;
                    float4 bq = *(const float4*)(p + 4);
                    v[0] += w * a.x;  v[1] += w * a.y;
                    v[2] += w * a.z;  v[3] += w * a.w;
                    v[4] += w * bq.x; v[5] += w * bq.y;
                    v[6] += w * bq.z; v[7] += w * bq.w;
                }
                ushort4 hv1, lv1, hv2, lv2;
                bsplit(v[0], hv1.x, lv1.x); bsplit(v[1], hv1.y, lv1.y);
                bsplit(v[2], hv1.z, lv1.z); bsplit(v[3], hv1.w, lv1.w);
                bsplit(v[4], hv2.x, lv2.x); bsplit(v[5], hv2.y, lv2.y);
                bsplit(v[6], hv2.z, lv2.z); bsplit(v[7], hv2.w, lv2.w);
                *(ushort4*)&sAH[rr * 40 + c8 * 8] = hv1;
                *(ushort4*)&sAH[rr * 40 + c8 * 8 + 4] = hv2;
                *(ushort4*)&sAL[rr * 40 + c8 * 8] = lv1;
                *(ushort4*)&sAL[rr * 40 + c8 * 8 + 4] = lv2;
            }
        }
    };

    stage(0, 0);
    CP_COMMIT();

    for (int ch = 0; ch < 16; ch++) {
        CP_WAIT(0);
        __syncthreads();
        if (ch < 15) {
            stage(ch + 1, (ch + 1) & 1);
            CP_COMMIT();
        }
        const __nv_bfloat16* sAH =
            (const __nv_bfloat16*)(dyn + (ch & 1) * PG_BUF + PG_AH);
        const __nv_bfloat16* sAL =
            (const __nv_bfloat16*)(dyn + (ch & 1) * PG_BUF + PG_AL);
        const __nv_bfloat16* sBH =
            (const __nv_bfloat16*)(dyn + (ch & 1) * PG_BUF + PG_BH);
        const __nv_bfloat16* sBL =
            (const __nv_bfloat16*)(dyn + (ch & 1) * PG_BUF + PG_BL);

        #pragma unroll
        for (int ks = 0; ks < 2; ks++) {
            int ac = ks * 16 + cc;
            uint32_t aH[2][4], aL[2][4];
            #pragma unroll
            for (int mt = 0; mt < 2; mt++) {
                int ar = warpM * 32 + mt * 16 + r;
                aH[mt][0] = *(uint32_t*)&sAH[ar * 40 + ac];
                aH[mt][1] = *(uint32_t*)&sAH[(ar + 8) * 40 + ac];
                aH[mt][2] = *(uint32_t*)&sAH[ar * 40 + ac + 8];
                aH[mt][3] = *(uint32_t*)&sAH[(ar + 8) * 40 + ac + 8];
                aL[mt][0] = *(uint32_t*)&sAL[ar * 40 + ac];
                aL[mt][1] = *(uint32_t*)&sAL[(ar + 8) * 40 + ac];
                aL[mt][2] = *(uint32_t*)&sAL[ar * 40 + ac + 8];
                aL[mt][3] = *(uint32_t*)&sAL[(ar + 8) * 40 + ac + 8];
            }
            #pragma unroll
            for (int nt = 0; nt < 8; nt++) {
                int bn = warpN * 64 + nt * 8 + r;
                uint32_t bH[2], bL[2];
                bH[0] = *(uint32_t*)&sBH[bn * 40 + ac];
                bH[1] = *(uint32_t*)&sBH[bn * 40 + ac + 8];
                bL[0] = *(uint32_t*)&sBL[bn * 40 + ac];
                bL[1] = *(uint32_t*)&sBL[bn * 40 + ac + 8];
                #pragma unroll
                for (int mt = 0; mt < 2; mt++) {
                    mma16816(acc[mt][nt], aH[mt], bH);
                    mma16816(acc[mt][nt], aH[mt], bL);
                    mma16816(acc[mt][nt], aL[mt], bH);
                }
            }
        }
    }

    #pragma unroll
    for (int mt = 0; mt < 2; mt++) {
        #pragma unroll
        for (int nt = 0; nt < 8; nt++) {
            int m = m0 + warpM * 32 + mt * 16 + r;
            int n = n0 + warpN * 64 + nt * 8 + cc;
            float2 v0 = make_float2(tanhf(acc[mt][nt][0]), tanhf(acc[mt][nt][1]));
            float2 v1 = make_float2(tanhf(acc[mt][nt][2]), tanhf(acc[mt][nt][3]));
            *(float2*)&out[(size_t)m * 256 + n] = v0;
            *(float2*)&out[(size_t)(m + 8) * 256 + n] = v1;
        }
    }
}

// ---------------------------------------------------------------------------
// Fused flash attention (round-8 committed version, fp32 partial epilogue)
// ---------------------------------------------------------------------------
#define O_AH0 0
#define O_AL0 9216
#define O_AH1 18432
#define O_AL1 27648
#define O_E   36864
#define O_PMAX 110592
#define O_PSUM 111104
#define A_TOTAL 111616

__device__ __forceinline__ void stage_chunk(uint32_t base, int abuf, int ch,
                                            size_t dpBase, size_t encBase,
                                            int s0, int tid)
{
    uint32_t ah = base + (abuf ? O_AH1 : O_AH0);
    uint32_t al = ah + 9216;
    uint32_t eh = base + O_E + ch * 18432;
    uint32_t el = eh + 9216;
    int kc = ch * 64;
    #pragma unroll
    for (int u = 0; u < 2; u++) {
        int f = tid + u * 256;
        int rr = f >> 3, c = f & 7;
        uint32_t doff = rr * 144 + c * 16;
        size_t ga = dpBase + (size_t)rr * 256 + kc + c * 8;
        size_t ge = encBase + (size_t)(s0 + rr) * 256 + kc + c * 8;
        cp16(ah + doff, g_dpH + ga);
        cp16(al + doff, g_dpL + ga);
        cp16(eh + doff, g_encH + ge);
        cp16(el + doff, g_encL + ge);
    }
}

__global__ __launch_bounds__(256, 2)
void attn_kernel()
{
    extern __shared__ char dyn[];
    uint32_t base = smem_u32(dyn);
    float* sPmax = (float*)(dyn + O_PMAX);
    float* sPsum = (float*)(dyn + O_PSUM);
    __nv_bfloat16* pH = (__nv_bfloat16*)(dyn + O_AH1);
    __nv_bfloat16* pL = (__nv_bfloat16*)(dyn + O_AL1);

    int tid = threadIdx.x, lane = tid & 31, wid = tid >> 5;
    int warpT = wid & 3;
    int warpS = wid >> 2;
    int r = lane >> 2, cc = (lane & 3) * 2;
    int b = blockIdx.y;
    int t0 = blockIdx.x * 64;
    int slice = blockIdx.z;
    int len = g_lengths[b];

    int sbeg = slice * SLICE_S;
    if (sbeg >= len) return;
    int send = min(sbeg + SLICE_S, len);

    size_t dpBase = ((size_t)b * Tt + t0) * 256;
    size_t encBase = (size_t)b * Ss * 256;

    int row0 = warpT * 16 + r;
    int row1 = row0 + 8;
    float mreg0 = -1e30f, mreg1 = -1e30f;
    float lreg0 = 0.f, lreg1 = 0.f;

    float ctx[4][4][4];
    #pragma unroll
    for (int i = 0; i < 4; i++)
        #pragma unroll
        for (int j = 0; j < 4; j++)
            #pragma unroll
            for (int q = 0; q < 4; q++) ctx[i][j][q] = 0.f;

    stage_chunk(base, 0, 0, dpBase, encBase, sbeg, tid);
    CP_COMMIT();

    for (int s0 = sbeg; s0 < send; s0 += 64) {
        bool have_next = (s0 + 64 < send);

        float sacc[4][4];
        #pragma unroll
        for (int j = 0; j < 4; j++)
            #pragma unroll
            for (int q = 0; q < 4; q++) sacc[j][q] = 0.f;

        #pragma unroll
        for (int kch = 0; kch < 4; kch++) {
            if (kch < 3) {
                stage_chunk(base, (kch + 1) & 1, kch + 1, dpBase, encBase,
                            s0, tid);
                CP_COMMIT();
                CP_WAIT(1);
            } else {
                CP_WAIT(0);
            }
            __syncthreads();

            const __nv_bfloat16* sAH =
                (const __nv_bfloat16*)(dyn + ((kch & 1) ? O_AH1 : O_AH0));
            const __nv_bfloat16* sAL = sAH + 4608;
            const __nv_bfloat16* sBH =
                (const __nv_bfloat16*)(dyn + O_E + kch * 18432);
            const __nv_bfloat16* sBL = sBH + 4608;

            #pragma unroll
            for (int ks = 0; ks < 4; ks++) {
                int ac = ks * 16 + cc;
                int ar = warpT * 16 + r;
                uint32_t aH[4], aL[4];
                aH[0] = *(uint32_t*)&sAH[ar * 72 + ac];
                aH[1] = *(uint32_t*)&sAH[(ar + 8) * 72 + ac];
                aH[2] = *(uint32_t*)&sAH[ar * 72 + ac + 8];
                aH[3] = *(uint32_t*)&sAH[(ar + 8) * 72 + ac + 8];
                aL[0] = *(uint32_t*)&sAL[ar * 72 + ac];
                aL[1] = *(uint32_t*)&sAL[(ar + 8) * 72 + ac];
                aL[2] = *(uint32_t*)&sAL[ar * 72 + ac + 8];
                aL[3] = *(uint32_t*)&sAL[(ar + 8) * 72 + ac + 8];
                #pragma unroll
                for (int nt = 0; nt < 4; nt++) {
                    int bn = warpS * 32 + nt * 8 + r;
                    uint32_t bH[2], bL[2];
                    bH[0] = *(uint32_t*)&sBH[bn * 72 + ac];
                    bH[1] = *(uint32_t*)&sBH[bn * 72 + ac + 8];
                    bL[0] = *(uint32_t*)&sBL[bn * 72 + ac];
                    bL[1] = *(uint32_t*)&sBL[bn * 72 + ac + 8];
                    mma16816(sacc[nt], aH, bH);
                    mma16816(sacc[nt], aH, bL);
                    mma16816(sacc[nt], aL, bH);
                }
            }
            __syncthreads();
        }

        // register softmax
        float rm0 = -1e30f, rm1 = -1e30f;
        #pragma unroll
        for (int nt = 0; nt < 4; nt++) {
            int cg = s0 + warpS * 32 + nt * 8 + cc;
            if (cg >= len)     { sacc[nt][0] = -1e30f; sacc[nt][2] = -1e30f; }
            if (cg + 1 >= len) { sacc[nt][1] = -1e30f; sacc[nt][3] = -1e30f; }
            rm0 = fmaxf(rm0, fmaxf(sacc[nt][0], sacc[nt][1]));
            rm1 = fmaxf(rm1, fmaxf(sacc[nt][2], sacc[nt][3]));
        }
        rm0 = fmaxf(rm0, __shfl_xor_sync(0xffffffffu, rm0, 1));
        rm0 = fmaxf(rm0, __shfl_xor_sync(0xffffffffu, rm0, 2));
        rm1 = fmaxf(rm1, __shfl_xor_sync(0xffffffffu, rm1, 1));
        rm1 = fmaxf(rm1, __shfl_xor_sync(0xffffffffu, rm1, 2));
        if ((lane & 3) == 0) {
            sPmax[row0 * 2 + warpS] = rm0;
            sPmax[row1 * 2 + warpS] = rm1;
        }
        __syncthreads();

        float mN0 = fmaxf(mreg0, fmaxf(sPmax[row0 * 2], sPmax[row0 * 2 + 1]));
        float mN1 = fmaxf(mreg1, fmaxf(sPmax[row1 * 2], sPmax[row1 * 2 + 1]));
        float scl0 = __expf(mreg0 - mN0);
        float scl1 = __expf(mreg1 - mN1);
        mreg0 = mN0; mreg1 = mN1;

        float sum0 = 0.f, sum1 = 0.f;
        #pragma unroll
        for (int nt = 0; nt < 4; nt++) {
            sacc[nt][0] = __expf(sacc[nt][0] - mN0);
            sacc[nt][1] = __expf(sacc[nt][1] - mN0);
            sacc[nt][2] = __expf(sacc[nt][2] - mN1);
            sacc[nt][3] = __expf(sacc[nt][3] - mN1);
            sum0 += sacc[nt][0] + sacc[nt][1];
            sum1 += sacc[nt][2] + sacc[nt][3];
        }
        sum0 += __shfl_xor_sync(0xffffffffu, sum0, 1);
        sum0 += __shfl_xor_sync(0xffffffffu, sum0, 2);
        sum1 += __shfl_xor_sync(0xffffffffu, sum1, 1);
        sum1 += __shfl_xor_sync(0xffffffffu, sum1, 2);
        if ((lane & 3) == 0) {
            sPsum[row0 * 2 + warpS] = sum0;
            sPsum[row1 * 2 + warpS] = sum1;
        }
        #pragma unroll
        for (int nt = 0; nt < 4; nt++) {
            int colb = warpS * 32 + nt * 8 + cc;
            unsigned short h0, l0, h1, l1, h2, l2, h3, l3;
            bsplit(sacc[nt][0], h0, l0); bsplit(sacc[nt][1], h1, l1);
            bsplit(sacc[nt][2], h2, l2); bsplit(sacc[nt][3], h3, l3);
            *(uint32_t*)&pH[row0 * 72 + colb] = pack2(h0, h1);
            *(uint32_t*)&pL[row0 * 72 + colb] = pack2(l0, l1);
            *(uint32_t*)&pH[row1 * 72 + colb] = pack2(h2, h3);
            *(uint32_t*)&pL[row1 * 72 + colb] = pack2(l2, l3);
        }
        __syncthreads();

        lreg0 = lreg0 * scl0 + sPsum[row0 * 2] + sPsum[row0 * 2 + 1];
        lreg1 = lreg1 * scl1 + sPsum[row1 * 2] + sPsum[row1 * 2 + 1];
        #pragma unroll
        for (int i = 0; i < 4; i++)
            #pragma unroll
            for (int j = 0; j < 4; j++) {
                ctx[i][j][0] *= scl0; ctx[i][j][1] *= scl0;
                ctx[i][j][2] *= scl1; ctx[i][j][3] *= scl1;
            }

        // context GEMM (reuse E chunks)
        #pragma unroll
        for (int ch = 0; ch < 4; ch++) {
            uint32_t ehb = base + O_E + ch * 18432;
            uint32_t elb = ehb + 9216;
            #pragma unroll
            for (int ks = 0; ks < 4; ks++) {
                int ac = ks * 16 + cc;
                int ar = warpT * 16 + r;
                uint32_t aH[4], aL[4];
                aH[0] = *(uint32_t*)&pH[ar * 72 + ac];
                aH[1] = *(uint32_t*)&pH[(ar + 8) * 72 + ac];
                aH[2] = *(uint32_t*)&pH[ar * 72 + ac + 8];
                aH[3] = *(uint32_t*)&pH[(ar + 8) * 72 + ac + 8];
                aL[0] = *(uint32_t*)&pL[ar * 72 + ac];
                aL[1] = *(uint32_t*)&pL[(ar + 8) * 72 + ac];
                aL[2] = *(uint32_t*)&pL[ar * 72 + ac + 8];
                aL[3] = *(uint32_t*)&pL[(ar + 8) * 72 + ac + 8];
                uint32_t lrow = (uint32_t)(ks * 16 + (lane & 15));
                uint32_t lcol0 = (uint32_t)(warpS * 32 + ((lane >> 4) << 3));
                #pragma unroll
                for (int pair = 0; pair < 2; pair++) {
                    uint32_t off = (lrow * 72 + lcol0 + pair * 16) * 2;
                    uint32_t bh0, bh1, bh2, bh3, bl0, bl1, bl2, bl3;
                    ldsm_x4_t(bh0, bh1, bh2, bh3, ehb + off);
                    ldsm_x4_t(bl0, bl1, bl2, bl3, elb + off);
                    uint32_t bH0[2] = {bh0, bh1}, bH1[2] = {bh2, bh3};
                    uint32_t bL0[2] = {bl0, bl1}, bL1[2] = {bl2, bl3};
                    int nt = pair * 2;
                    mma16816(ctx[ch][nt], aH, bH0);
                    mma16816(ctx[ch][nt], aH, bL0);
                    mma16816(ctx[ch][nt], aL, bH0);
                    mma16816(ctx[ch][nt + 1], aH, bH1);
                    mma16816(ctx[ch][nt + 1], aH, bL1);
                    mma16816(ctx[ch][nt + 1], aL, bH1);
                }
            }
            if (ch == 0) {
                __syncthreads();
                if (have_next) {
                    stage_chunk(base, 0, 0, dpBase, encBase, s0 + 64, tid);
                    CP_COMMIT();
                }
            }
        }
        __syncthreads();
    }

    // write partials (fp32)
    size_t pmBase = (((size_t)slice * Bb + b) * Tt) + t0;
    if (warpS == 0 && (lane & 3) == 0) {
        g_pm[pmBase + row0] = mreg0;
        g_pm[pmBase + row1] = mreg1;
        g_pl[pmBase + row0] = lreg0;
        g_pl[pmBase + row1] = lreg1;
    }
    int t = t0 + row0;
    size_t obase = (((size_t)slice * Bb + b) * Tt + t) * 256;
    #pragma unroll
    for (int ch = 0; ch < 4; ch++) {
        #pragma unroll
        for (int nt = 0; nt < 4; nt++) {
            int e = ch * 64 + warpS * 32 + nt * 8 + cc;
            *(float2*)&g_pctx[obase + e] =
                make_float2(ctx[ch][nt][0], ctx[ch][nt][1]);
            *(float2*)&g_pctx[obase + 8 * 256 + e] =
                make_float2(ctx[ch][nt][2], ctx[ch][nt][3]);
        }
    }
}

// ---------------------------------------------------------------------------
extern "C" void kernel_launch(void* const* d_in, const int* in_sizes, int n_in,
                              void* d_out, int out_size)
{
    (void)in_sizes; (void)n_in; (void)out_size;
    const float* enc = (const float*)d_in[0];
    const float* dec = (const float*)d_in[1];
    const unsigned char* mask = (const unsigned char*)d_in[2];
    const float* W_enc = (const float*)d_in[3];
    const float* W_fin = (const float*)d_in[4];
    float* out = (float*)d_out;

    void *pDecH, *pDecL, *pDpH, *pDpL, *pWeH, *pWeL, *pWfH, *pWfL;
    cudaGetSymbolAddress(&pDecH, g_decH);
    cudaGetSymbolAddress(&pDecL, g_decL);
    cudaGetSymbolAddress(&pDpH, g_dpH);
    cudaGetSymbolAddress(&pDpL, g_dpL);
    cudaGetSymbolAddress(&pWeH, g_WencH);
    cudaGetSymbolAddress(&pWeL, g_WencL);
    cudaGetSymbolAddress(&pWfH, g_WfinTH);
    cudaGetSymbolAddress(&pWfL, g_WfinTL);

    cudaFuncSetAttribute((const void*)mma_gemm1_kernel,
                         cudaFuncAttributeMaxDynamicSharedMemorySize, PG_TOTAL);
    cudaFuncSetAttribute((const void*)mma_gemm3_fused,
                         cudaFuncAttributeMaxDynamicSharedMemorySize, PG_TOTAL);
    cudaFuncSetAttribute((const void*)attn_kernel,
                         cudaFuncAttributeMaxDynamicSharedMemorySize, A_TOTAL);

    detect_lengths_kernel<<<1, 256>>>(mask);
    prep_convert_kernel<<<1024, 256>>>(enc, dec, W_enc, W_fin);

    // GEMM1': decproj = dec @ W_enc^T
    dim3 g1(2, 128);
    mma_gemm1_kernel<<<g1, 256, PG_TOTAL>>>(
        (const __nv_bfloat16*)pDecH, (const __nv_bfloat16*)pDecL,
        (const __nv_bfloat16*)pWeH, (const __nv_bfloat16*)pWeL,
        (__nv_bfloat16*)pDpH, (__nv_bfloat16*)pDpL);

    dim3 g2(Tt / 64, Bb, NSLICE);
    attn_kernel<<<g2, 256, A_TOTAL>>>();

    // GEMM3 fused with combine (weights computed in-kernel)
    dim3 g3(2, 128);
    mma_gemm3_fused<<<g3, 256, PG_TOTAL>>>(
        (const __nv_bfloat16*)pDecH, (const __nv_bfloat16*)pDecL,
        (const __nv_bfloat16*)pWfH, (const __nv_bfloat16*)pWfL,
        out);
}

// round 12
// speedup vs baseline: 1.4991x; 1.0044x over previous
#include <cuda_runtime.h>
#include <cuda_bf16.h>
#include <math.h>
#include <stdint.h>

#define Bb 16
#define Ss 2048
#define Tt 1024
#define Ee 256
#define Dd 256
#define NSLICE 4
#define SLICE_S 512
#define MTOT (Bb * Tt)   // 16384

// ---------------------------------------------------------------------------
// Scratch (allocation-free device globals), bf16 hi/lo split representations.
// dec is consumed as fp32 directly by the GEMMs (converted during staging).
// ---------------------------------------------------------------------------
__device__ __nv_bfloat16 g_encH[Bb * Ss * Ee];
__device__ __nv_bfloat16 g_encL[Bb * Ss * Ee];
__device__ __nv_bfloat16 g_dpH[Bb * Tt * Ee];     // decproj hi
__device__ __nv_bfloat16 g_dpL[Bb * Tt * Ee];     // decproj lo
__device__ __nv_bfloat16 g_WencH[Ee * Dd];        // W_enc native [e][d]
__device__ __nv_bfloat16 g_WencL[Ee * Dd];
__device__ __nv_bfloat16 g_WfinTH[Dd * (Ee + Dd)];
__device__ __nv_bfloat16 g_WfinTL[Dd * (Ee + Dd)];
__device__ int g_lengths[Bb];
__device__ float g_pctx[NSLICE * MTOT * Ee];      // fp32 split-KV partials
__device__ float g_pm[NSLICE * MTOT];
__device__ float g_pl[NSLICE * MTOT];

// ---------------------------------------------------------------------------
// Helpers
// ---------------------------------------------------------------------------
__device__ __forceinline__ uint32_t smem_u32(const void* p) {
    uint32_t a;
    asm("{ .reg .u64 t; cvta.to.shared.u64 t, %1; cvt.u32.u64 %0, t; }"
        : "=r"(a) : "l"(p));
    return a;
}

__device__ __forceinline__ void mma16816(float* d, const uint32_t* a,
                                         const uint32_t* b) {
    asm volatile(
        "mma.sync.aligned.m16n8k16.row.col.f32.bf16.bf16.f32 "
        "{%0,%1,%2,%3}, {%4,%5,%6,%7}, {%8,%9}, {%0,%1,%2,%3};"
        : "+f"(d[0]), "+f"(d[1]), "+f"(d[2]), "+f"(d[3])
        : "r"(a[0]), "r"(a[1]), "r"(a[2]), "r"(a[3]), "r"(b[0]), "r"(b[1]));
}

__device__ __forceinline__ void ldsm_x4_t(uint32_t& r0, uint32_t& r1,
                                          uint32_t& r2, uint32_t& r3,
                                          uint32_t addr) {
    asm volatile("ldmatrix.sync.aligned.m8n8.x4.trans.shared.b16 "
                 "{%0,%1,%2,%3}, [%4];"
                 : "=r"(r0), "=r"(r1), "=r"(r2), "=r"(r3) : "r"(addr));
}

__device__ __forceinline__ void cp16(uint32_t dst, const void* src) {
    asm volatile("cp.async.cg.shared.global [%0], [%1], 16;"
                 :: "r"(dst), "l"(src));
}
#define CP_COMMIT() asm volatile("cp.async.commit_group;")
#define CP_WAIT(N)  asm volatile("cp.async.wait_group %0;" :: "n"(N))

__device__ __forceinline__ void bsplit(float x, unsigned short& h,
                                       unsigned short& l) {
    __nv_bfloat16 hb = __float2bfloat16(x);
    __nv_bfloat16 lb = __float2bfloat16(x - __bfloat162float(hb));
    h = *(unsigned short*)&hb;
    l = *(unsigned short*)&lb;
}

__device__ __forceinline__ uint32_t pack2(unsigned short a, unsigned short b) {
    return (uint32_t)a | ((uint32_t)b << 16);
}

// ---------------------------------------------------------------------------
// Mask prologue (handles uint8 or int32 bool encodings)
// ---------------------------------------------------------------------------
__global__ void detect_lengths_kernel(const unsigned char* __restrict__ mask)
{
    __shared__ int s_flag;
    __shared__ int s_cnt[Bb];
    int tid = threadIdx.x;
    if (tid == 0) s_flag = 0;
    if (tid < Bb) s_cnt[tid] = 0;
    __syncthreads();

    int local = 0;
    for (int i = tid; i < Bb * Ss; i += 256)
        if ((i & 3) != 0 && mask[i] != 0) local = 1;
    if (local) atomicOr(&s_flag, 1);
    __syncthreads();

    bool isU8 = (s_flag != 0);
    int row = tid >> 4, part = tid & 15;
    int cnt = 0;
    if (isU8) {
        const unsigned char* p = mask + row * Ss + part * 128;
        #pragma unroll 4
        for (int e = 0; e < 128; e++) cnt += (p[e] != 0);
    } else {
        const int* p = ((const int*)mask) + row * Ss + part * 128;
        #pragma unroll 4
        for (int e = 0; e < 128; e++) cnt += (p[e] != 0);
    }
    atomicAdd(&s_cnt[row], cnt);
    __syncthreads();
    if (tid < Bb) g_lengths[tid] = s_cnt[tid];
}

// ---------------------------------------------------------------------------
// Prep: fp32 -> bf16 hi/lo for enc; W_enc split; W_fin transposed+split.
// (dec conversion moved into the GEMM staging paths)
// ---------------------------------------------------------------------------
__global__ void prep_convert_kernel(const float* __restrict__ enc,
                                    const float* __restrict__ Wenc,
                                    const float* __restrict__ Wfin)
{
    int tid = blockIdx.x * blockDim.x + threadIdx.x;
    int stride = gridDim.x * blockDim.x;

    const int NE4 = (Bb * Ss * Ee) / 4;
    for (int i = tid; i < NE4; i += stride) {
        float4 v = ((const float4*)enc)[i];
        ushort4 hv, lv;
        bsplit(v.x, hv.x, lv.x); bsplit(v.y, hv.y, lv.y);
        bsplit(v.z, hv.z, lv.z); bsplit(v.w, hv.w, lv.w);
        ((ushort4*)g_encH)[i] = hv;
        ((ushort4*)g_encL)[i] = lv;
    }
    for (int i = tid; i < 256 * 256; i += stride) {
        unsigned short h, l;
        bsplit(Wenc[i], h, l);
        *(unsigned short*)&g_WencH[i] = h;
        *(unsigned short*)&g_WencL[i] = l;
    }
    for (int i = tid; i < 256 * 512; i += stride) {
        int d = i >> 9, f = i & 511;
        unsigned short h, l;
        bsplit(Wfin[f * 256 + d], h, l);
        *(unsigned short*)&g_WfinTH[i] = h;
        *(unsigned short*)&g_WfinTL[i] = l;
    }
}

// ---------------------------------------------------------------------------
// Pipelined GEMM smem: 32-wide k-chunks, stride 40 shorts (80 B) per row,
// double-buffered. Buffer = 4 matrices (Ah,Al,Bh,Bl) x 128 rows x 80 B.
// ---------------------------------------------------------------------------
#define PG_MAT   10240          // 128 * 80
#define PG_BUF   (4 * PG_MAT)   // 40960
#define PG_TOTAL (2 * PG_BUF)   // 81920
#define PG_AH 0
#define PG_AL PG_MAT
#define PG_BH (2 * PG_MAT)
#define PG_BL (3 * PG_MAT)

// stage fp32 A rows into split bf16 hi/lo smem (LDG + split + STS)
__device__ __forceinline__ void stageA_f32(char* dyn, int buf, int m0,
                                           const float* __restrict__ Af,
                                           int kc, int tid)
{
    __nv_bfloat16* sAH = (__nv_bfloat16*)(dyn + buf * PG_BUF + PG_AH);
    __nv_bfloat16* sAL = (__nv_bfloat16*)(dyn + buf * PG_BUF + PG_AL);
    #pragma unroll
    for (int u = 0; u < 2; u++) {
        int f = tid + u * 256;
        int rr = f >> 2, c = f & 3;
        const float* p = &Af[(size_t)(m0 + rr) * 256 + kc + c * 8];
        float4 a = *(const float4*)p;
        float4 b = *(const float4*)(p + 4);
        ushort4 hv1, lv1, hv2, lv2;
        bsplit(a.x, hv1.x, lv1.x); bsplit(a.y, hv1.y, lv1.y);
        bsplit(a.z, hv1.z, lv1.z); bsplit(a.w, hv1.w, lv1.w);
        bsplit(b.x, hv2.x, lv2.x); bsplit(b.y, hv2.y, lv2.y);
        bsplit(b.z, hv2.z, lv2.z); bsplit(b.w, hv2.w, lv2.w);
        *(ushort4*)&sAH[rr * 40 + c * 8] = hv1;
        *(ushort4*)&sAH[rr * 40 + c * 8 + 4] = hv2;
        *(ushort4*)&sAL[rr * 40 + c * 8] = lv1;
        *(ushort4*)&sAL[rr * 40 + c * 8 + 4] = lv2;
    }
}

// ---------------------------------------------------------------------------
// GEMM1' (decproj = dec_fp32 @ W_enc^T), K=256, 8 chunks, pipelined.
// A converted fp32->hi/lo during staging; B via cp.async.
// ---------------------------------------------------------------------------
__global__ __launch_bounds__(256, 2)
void mma_gemm1_kernel(const float* __restrict__ decf,
                      const __nv_bfloat16* __restrict__ BTH,
                      const __nv_bfloat16* __restrict__ BTL,
                      __nv_bfloat16* __restrict__ CH,
                      __nv_bfloat16* __restrict__ CL)
{
    extern __shared__ char dyn[];
    uint32_t base = smem_u32(dyn);

    int tid = threadIdx.x, lane = tid & 31, wid = tid >> 5;
    int warpM = wid & 3, warpN = wid >> 2;
    int m0 = blockIdx.y * 128, n0 = blockIdx.x * 128;
    int r = lane >> 2, cc = (lane & 3) * 2;

    float acc[2][8][4];
    #pragma unroll
    for (int i = 0; i < 2; i++)
        #pragma unroll
        for (int j = 0; j < 8; j++)
            #pragma unroll
            for (int q = 0; q < 4; q++) acc[i][j][q] = 0.f;

    auto stageB = [&](int ch, int buf) {
        uint32_t bb = base + buf * PG_BUF;
        int kc = ch * 32;
        #pragma unroll
        for (int u = 0; u < 2; u++) {
            int f = tid + u * 256;
            int rr = f >> 2, c = f & 3;
            uint32_t doff = rr * 80 + c * 16;
            size_t gb = (size_t)(n0 + rr) * 256 + kc + c * 8;
            cp16(bb + PG_BH + doff, BTH + gb);
            cp16(bb + PG_BL + doff, BTL + gb);
        }
    };

    stageB(0, 0);
    CP_COMMIT();
    stageA_f32(dyn, 0, m0, decf, 0, tid);

    for (int ch = 0; ch < 8; ch++) {
        CP_WAIT(0);
        __syncthreads();
        if (ch < 7) {
            stageB(ch + 1, (ch + 1) & 1);
            CP_COMMIT();
            stageA_f32(dyn, (ch + 1) & 1, m0, decf, (ch + 1) * 32, tid);
        }
        const __nv_bfloat16* sAH =
            (const __nv_bfloat16*)(dyn + (ch & 1) * PG_BUF + PG_AH);
        const __nv_bfloat16* sAL =
            (const __nv_bfloat16*)(dyn + (ch & 1) * PG_BUF + PG_AL);
        const __nv_bfloat16* sBH =
            (const __nv_bfloat16*)(dyn + (ch & 1) * PG_BUF + PG_BH);
        const __nv_bfloat16* sBL =
            (const __nv_bfloat16*)(dyn + (ch & 1) * PG_BUF + PG_BL);

        #pragma unroll
        for (int ks = 0; ks < 2; ks++) {
            int ac = ks * 16 + cc;
            uint32_t aH[2][4], aL[2][4];
            #pragma unroll
            for (int mt = 0; mt < 2; mt++) {
                int ar = warpM * 32 + mt * 16 + r;
                aH[mt][0] = *(uint32_t*)&sAH[ar * 40 + ac];
                aH[mt][1] = *(uint32_t*)&sAH[(ar + 8) * 40 + ac];
                aH[mt][2] = *(uint32_t*)&sAH[ar * 40 + ac + 8];
                aH[mt][3] = *(uint32_t*)&sAH[(ar + 8) * 40 + ac + 8];
                aL[mt][0] = *(uint32_t*)&sAL[ar * 40 + ac];
                aL[mt][1] = *(uint32_t*)&sAL[(ar + 8) * 40 + ac];
                aL[mt][2] = *(uint32_t*)&sAL[ar * 40 + ac + 8];
                aL[mt][3] = *(uint32_t*)&sAL[(ar + 8) * 40 + ac + 8];
            }
            #pragma unroll
            for (int nt = 0; nt < 8; nt++) {
                int bn = warpN * 64 + nt * 8 + r;
                uint32_t bH[2], bL[2];
                bH[0] = *(uint32_t*)&sBH[bn * 40 + ac];
                bH[1] = *(uint32_t*)&sBH[bn * 40 + ac + 8];
                bL[0] = *(uint32_t*)&sBL[bn * 40 + ac];
                bL[1] = *(uint32_t*)&sBL[bn * 40 + ac + 8];
                #pragma unroll
                for (int mt = 0; mt < 2; mt++) {
                    mma16816(acc[mt][nt], aH[mt], bH);
                    mma16816(acc[mt][nt], aH[mt], bL);
                    mma16816(acc[mt][nt], aL[mt], bH);
                }
            }
        }
    }

    #pragma unroll
    for (int mt = 0; mt < 2; mt++) {
        #pragma unroll
        for (int nt = 0; nt < 8; nt++) {
            int m = m0 + warpM * 32 + mt * 16 + r;
            int n = n0 + warpN * 64 + nt * 8 + cc;
            unsigned short h0, l0, h1, l1, h2, l2, h3, l3;
            bsplit(acc[mt][nt][0], h0, l0); bsplit(acc[mt][nt][1], h1, l1);
            bsplit(acc[mt][nt][2], h2, l2); bsplit(acc[mt][nt][3], h3, l3);
            *(uint32_t*)&CH[(size_t)m * 256 + n] = pack2(h0, h1);
            *(uint32_t*)&CL[(size_t)m * 256 + n] = pack2(l0, l1);
            *(uint32_t*)&CH[(size_t)(m + 8) * 256 + n] = pack2(h2, h3);
            *(uint32_t*)&CL[(size_t)(m + 8) * 256 + n] = pack2(l2, l3);
        }
    }
}

// ---------------------------------------------------------------------------
// GEMM3 fused with combine: out = tanh([ctx | dec] @ W_fin). ctx merged
// in-register from fp32 split-KV partials (active slices only); dec chunks
// converted fp32->hi/lo during staging; combine weights in prologue.
// ---------------------------------------------------------------------------
__global__ __launch_bounds__(256, 2)
void mma_gemm3_fused(const float* __restrict__ decf,
                     const __nv_bfloat16* __restrict__ BTH,
                     const __nv_bfloat16* __restrict__ BTL,
                     float* __restrict__ out)
{
    extern __shared__ char dyn[];
    __shared__ float wsm[128][4];
    uint32_t base = smem_u32(dyn);

    int tid = threadIdx.x, lane = tid & 31, wid = tid >> 5;
    int warpM = wid & 3, warpN = wid >> 2;
    int m0 = blockIdx.y * 128, n0 = blockIdx.x * 128;
    int r = lane >> 2, cc = (lane & 3) * 2;
    int nsl = min(NSLICE, (g_lengths[m0 >> 10] + SLICE_S - 1) / SLICE_S);

    // combine weights for this CTA's 128 rows
    if (tid < 128) {
        int m = m0 + tid;
        float mv[4], lv[4];
        float M = -1e30f;
        for (int s = 0; s < nsl; s++) {
            mv[s] = g_pm[s * MTOT + m];
            lv[s] = g_pl[s * MTOT + m];
            M = fmaxf(M, mv[s]);
        }
        float L = 0.f, ws[4];
        for (int s = 0; s < nsl; s++) {
            float e = __expf(mv[s] - M);
            ws[s] = e;
            L += e * lv[s];
        }
        float inv = 1.0f / L;
        #pragma unroll
        for (int s = 0; s < 4; s++)
            wsm[tid][s] = (s < nsl) ? ws[s] * inv : 0.f;
    }
    __syncthreads();

    float wreg[2][4];
    #pragma unroll
    for (int u = 0; u < 2; u++) {
        int rr = (tid + u * 256) >> 2;
        #pragma unroll
        for (int s = 0; s < 4; s++)
            wreg[u][s] = wsm[rr][s];
    }

    float acc[2][8][4];
    #pragma unroll
    for (int i = 0; i < 2; i++)
        #pragma unroll
        for (int j = 0; j < 8; j++)
            #pragma unroll
            for (int q = 0; q < 4; q++) acc[i][j][q] = 0.f;

    auto stage = [&](int ch, int buf) {
        uint32_t bb = base + buf * PG_BUF;
        int kc = ch * 32;
        #pragma unroll
        for (int u = 0; u < 2; u++) {
            int f = tid + u * 256;
            int rr = f >> 2, c = f & 3;
            uint32_t doff = rr * 80 + c * 16;
            size_t gb = (size_t)(n0 + rr) * 512 + kc + c * 8;
            cp16(bb + PG_BH + doff, BTH + gb);
            cp16(bb + PG_BL + doff, BTL + gb);
        }
        if (ch >= 8) {
            stageA_f32(dyn, buf, m0, decf, kc - 256, tid);
        } else {
            __nv_bfloat16* sAH = (__nv_bfloat16*)(dyn + buf * PG_BUF + PG_AH);
            __nv_bfloat16* sAL = (__nv_bfloat16*)(dyn + buf * PG_BUF + PG_AL);
            #pragma unroll
            for (int u = 0; u < 2; u++) {
                int f = tid + u * 256;
                int rr = f >> 2, c8 = f & 3;
                int m = m0 + rr;
                float v[8] = {0, 0, 0, 0, 0, 0, 0, 0};
                for (int s = 0; s < nsl; s++) {
                    float w = wreg[u][s];
                    const float* p =
                        &g_pctx[((size_t)s * MTOT + m) * 256 + kc + c8 * 8];
                    float4 a = *(const float4*)p;
                    float4 bq = *(const float4*)(p + 4);
                    v[0] += w * a.x;  v[1] += w * a.y;
                    v[2] += w * a.z;  v[3] += w * a.w;
                    v[4] += w * bq.x; v[5] += w * bq.y;
                    v[6] += w * bq.z; v[7] += w * bq.w;
                }
                ushort4 hv1, lv1, hv2, lv2;
                bsplit(v[0], hv1.x, lv1.x); bsplit(v[1], hv1.y, lv1.y);
                bsplit(v[2], hv1.z, lv1.z); bsplit(v[3], hv1.w, lv1.w);
                bsplit(v[4], hv2.x, lv2.x); bsplit(v[5], hv2.y, lv2.y);
                bsplit(v[6], hv2.z, lv2.z); bsplit(v[7], hv2.w, lv2.w);
                *(ushort4*)&sAH[rr * 40 + c8 * 8] = hv1;
                *(ushort4*)&sAH[rr * 40 + c8 * 8 + 4] = hv2;
                *(ushort4*)&sAL[rr * 40 + c8 * 8] = lv1;
                *(ushort4*)&sAL[rr * 40 + c8 * 8 + 4] = lv2;
            }
        }
    };

    stage(0, 0);
    CP_COMMIT();

    for (int ch = 0; ch < 16; ch++) {
        CP_WAIT(0);
        __syncthreads();
        if (ch < 15) {
            stage(ch + 1, (ch + 1) & 1);
            CP_COMMIT();
        }
        const __nv_bfloat16* sAH =
            (const __nv_bfloat16*)(dyn + (ch & 1) * PG_BUF + PG_AH);
        const __nv_bfloat16* sAL =
            (const __nv_bfloat16*)(dyn + (ch & 1) * PG_BUF + PG_AL);
        const __nv_bfloat16* sBH =
            (const __nv_bfloat16*)(dyn + (ch & 1) * PG_BUF + PG_BH);
        const __nv_bfloat16* sBL =
            (const __nv_bfloat16*)(dyn + (ch & 1) * PG_BUF + PG_BL);

        #pragma unroll
        for (int ks = 0; ks < 2; ks++) {
            int ac = ks * 16 + cc;
            uint32_t aH[2][4], aL[2][4];
            #pragma unroll
            for (int mt = 0; mt < 2; mt++) {
                int ar = warpM * 32 + mt * 16 + r;
                aH[mt][0] = *(uint32_t*)&sAH[ar * 40 + ac];
                aH[mt][1] = *(uint32_t*)&sAH[(ar + 8) * 40 + ac];
                aH[mt][2] = *(uint32_t*)&sAH[ar * 40 + ac + 8];
                aH[mt][3] = *(uint32_t*)&sAH[(ar + 8) * 40 + ac + 8];
                aL[mt][0] = *(uint32_t*)&sAL[ar * 40 + ac];
                aL[mt][1] = *(uint32_t*)&sAL[(ar + 8) * 40 + ac];
                aL[mt][2] = *(uint32_t*)&sAL[ar * 40 + ac + 8];
                aL[mt][3] = *(uint32_t*)&sAL[(ar + 8) * 40 + ac + 8];
            }
            #pragma unroll
            for (int nt = 0; nt < 8; nt++) {
                int bn = warpN * 64 + nt * 8 + r;
                uint32_t bH[2], bL[2];
                bH[0] = *(uint32_t*)&sBH[bn * 40 + ac];
                bH[1] = *(uint32_t*)&sBH[bn * 40 + ac + 8];
                bL[0] = *(uint32_t*)&sBL[bn * 40 + ac];
                bL[1] = *(uint32_t*)&sBL[bn * 40 + ac + 8];
                #pragma unroll
                for (int mt = 0; mt < 2; mt++) {
                    mma16816(acc[mt][nt], aH[mt], bH);
                    mma16816(acc[mt][nt], aH[mt], bL);
                    mma16816(acc[mt][nt], aL[mt], bH);
                }
            }
        }
    }

    #pragma unroll
    for (int mt = 0; mt < 2; mt++) {
        #pragma unroll
        for (int nt = 0; nt < 8; nt++) {
            int m = m0 + warpM * 32 + mt * 16 + r;
            int n = n0 + warpN * 64 + nt * 8 + cc;
            float2 v0 = make_float2(tanhf(acc[mt][nt][0]), tanhf(acc[mt][nt][1]));
            float2 v1 = make_float2(tanhf(acc[mt][nt][2]), tanhf(acc[mt][nt][3]));
            *(float2*)&out[(size_t)m * 256 + n] = v0;
            *(float2*)&out[(size_t)(m + 8) * 256 + n] = v1;
        }
    }
}

// ---------------------------------------------------------------------------
// Fused flash attention: round-8 tile machinery, restructured sync schedule
// (stage-after-sync, one barrier per score chunk; no trailing tile sync).
// ---------------------------------------------------------------------------
#define O_AH0 0
#define O_AL0 9216
#define O_AH1 18432
#define O_AL1 27648
#define O_E   36864
#define O_PMAX 110592
#define O_PSUM 111104
#define A_TOTAL 111616

__device__ __forceinline__ void stage_chunk(uint32_t base, int abuf, int ch,
                                            size_t dpBase, size_t encBase,
                                            int s0, int tid)
{
    uint32_t ah = base + (abuf ? O_AH1 : O_AH0);
    uint32_t al = ah + 9216;
    uint32_t eh = base + O_E + ch * 18432;
    uint32_t el = eh + 9216;
    int kc = ch * 64;
    #pragma unroll
    for (int u = 0; u < 2; u++) {
        int f = tid + u * 256;
        int rr = f >> 3, c = f & 7;
        uint32_t doff = rr * 144 + c * 16;
        size_t ga = dpBase + (size_t)rr * 256 + kc + c * 8;
        size_t ge = encBase + (size_t)(s0 + rr) * 256 + kc + c * 8;
        cp16(ah + doff, g_dpH + ga);
        cp16(al + doff, g_dpL + ga);
        cp16(eh + doff, g_encH + ge);
        cp16(el + doff, g_encL + ge);
    }
}

__global__ __launch_bounds__(256, 2)
void attn_kernel()
{
    extern __shared__ char dyn[];
    uint32_t base = smem_u32(dyn);
    float* sPmax = (float*)(dyn + O_PMAX);
    float* sPsum = (float*)(dyn + O_PSUM);
    __nv_bfloat16* pH = (__nv_bfloat16*)(dyn + O_AH1);
    __nv_bfloat16* pL = (__nv_bfloat16*)(dyn + O_AL1);

    int tid = threadIdx.x, lane = tid & 31, wid = tid >> 5;
    int warpT = wid & 3;
    int warpS = wid >> 2;
    int r = lane >> 2, cc = (lane & 3) * 2;
    int b = blockIdx.y;
    int t0 = blockIdx.x * 64;
    int slice = blockIdx.z;
    int len = g_lengths[b];

    int sbeg = slice * SLICE_S;
    if (sbeg >= len) return;
    int send = min(sbeg + SLICE_S, len);

    size_t dpBase = ((size_t)b * Tt + t0) * 256;
    size_t encBase = (size_t)b * Ss * 256;

    int row0 = warpT * 16 + r;
    int row1 = row0 + 8;
    float mreg0 = -1e30f, mreg1 = -1e30f;
    float lreg0 = 0.f, lreg1 = 0.f;

    float ctx[4][4][4];
    #pragma unroll
    for (int i = 0; i < 4; i++)
        #pragma unroll
        for (int j = 0; j < 4; j++)
            #pragma unroll
            for (int q = 0; q < 4; q++) ctx[i][j][q] = 0.f;

    stage_chunk(base, 0, 0, dpBase, encBase, sbeg, tid);
    CP_COMMIT();

    for (int s0 = sbeg; s0 < send; s0 += 64) {
        bool have_next = (s0 + 64 < send);

        float sacc[4][4];
        #pragma unroll
        for (int j = 0; j < 4; j++)
            #pragma unroll
            for (int q = 0; q < 4; q++) sacc[j][q] = 0.f;

        // score GEMM: stage-after-sync pipeline, one barrier per chunk
        #pragma unroll
        for (int kch = 0; kch < 4; kch++) {
            CP_WAIT(0);
            __syncthreads();
            if (kch < 3) {
                stage_chunk(base, (kch + 1) & 1, kch + 1, dpBase, encBase,
                            s0, tid);
                CP_COMMIT();
            }

            const __nv_bfloat16* sAH =
                (const __nv_bfloat16*)(dyn + ((kch & 1) ? O_AH1 : O_AH0));
            const __nv_bfloat16* sAL = sAH + 4608;
            const __nv_bfloat16* sBH =
                (const __nv_bfloat16*)(dyn + O_E + kch * 18432);
            const __nv_bfloat16* sBL = sBH + 4608;

            #pragma unroll
            for (int ks = 0; ks < 4; ks++) {
                int ac = ks * 16 + cc;
                int ar = warpT * 16 + r;
                uint32_t aH[4], aL[4];
                aH[0] = *(uint32_t*)&sAH[ar * 72 + ac];
                aH[1] = *(uint32_t*)&sAH[(ar + 8) * 72 + ac];
                aH[2] = *(uint32_t*)&sAH[ar * 72 + ac + 8];
                aH[3] = *(uint32_t*)&sAH[(ar + 8) * 72 + ac + 8];
                aL[0] = *(uint32_t*)&sAL[ar * 72 + ac];
                aL[1] = *(uint32_t*)&sAL[(ar + 8) * 72 + ac];
                aL[2] = *(uint32_t*)&sAL[ar * 72 + ac + 8];
                aL[3] = *(uint32_t*)&sAL[(ar + 8) * 72 + ac + 8];
                #pragma unroll
                for (int nt = 0; nt < 4; nt++) {
                    int bn = warpS * 32 + nt * 8 + r;
                    uint32_t bH[2], bL[2];
                    bH[0] = *(uint32_t*)&sBH[bn * 72 + ac];
                    bH[1] = *(uint32_t*)&sBH[bn * 72 + ac + 8];
                    bL[0] = *(uint32_t*)&sBL[bn * 72 + ac];
                    bL[1] = *(uint32_t*)&sBL[bn * 72 + ac + 8];
                    mma16816(sacc[nt], aH, bH);
                    mma16816(sacc[nt], aH, bL);
                    mma16816(sacc[nt], aL, bH);
                }
            }
            // no trailing sync: next iteration's barrier (after CP_WAIT)
            // orders all reads of this A-buf before its next overwrite.
        }

        // register softmax
        float rm0 = -1e30f, rm1 = -1e30f;
        #pragma unroll
        for (int nt = 0; nt < 4; nt++) {
            int cg = s0 + warpS * 32 + nt * 8 + cc;
            if (cg >= len)     { sacc[nt][0] = -1e30f; sacc[nt][2] = -1e30f; }
            if (cg + 1 >= len) { sacc[nt][1] = -1e30f; sacc[nt][3] = -1e30f; }
            rm0 = fmaxf(rm0, fmaxf(sacc[nt][0], sacc[nt][1]));
            rm1 = fmaxf(rm1, fmaxf(sacc[nt][2], sacc[nt][3]));
        }
        rm0 = fmaxf(rm0, __shfl_xor_sync(0xffffffffu, rm0, 1));
        rm0 = fmaxf(rm0, __shfl_xor_sync(0xffffffffu, rm0, 2));
        rm1 = fmaxf(rm1, __shfl_xor_sync(0xffffffffu, rm1, 1));
        rm1 = fmaxf(rm1, __shfl_xor_sync(0xffffffffu, rm1, 2));
        if ((lane & 3) == 0) {
            sPmax[row0 * 2 + warpS] = rm0;
            sPmax[row1 * 2 + warpS] = rm1;
        }
        __syncthreads();

        float mN0 = fmaxf(mreg0, fmaxf(sPmax[row0 * 2], sPmax[row0 * 2 + 1]));
        float mN1 = fmaxf(mreg1, fmaxf(sPmax[row1 * 2], sPmax[row1 * 2 + 1]));
        float scl0 = __expf(mreg0 - mN0);
        float scl1 = __expf(mreg1 - mN1);
        mreg0 = mN0; mreg1 = mN1;

        float sum0 = 0.f, sum1 = 0.f;
        #pragma unroll
        for (int nt = 0; nt < 4; nt++) {
            sacc[nt][0] = __expf(sacc[nt][0] - mN0);
            sacc[nt][1] = __expf(sacc[nt][1] - mN0);
            sacc[nt][2] = __expf(sacc[nt][2] - mN1);
            sacc[nt][3] = __expf(sacc[nt][3] - mN1);
            sum0 += sacc[nt][0] + sacc[nt][1];
            sum1 += sacc[nt][2] + sacc[nt][3];
        }
        sum0 += __shfl_xor_sync(0xffffffffu, sum0, 1);
        sum0 += __shfl_xor_sync(0xffffffffu, sum0, 2);
        sum1 += __shfl_xor_sync(0xffffffffu, sum1, 1);
        sum1 += __shfl_xor_sync(0xffffffffu, sum1, 2);
        if ((lane & 3) == 0) {
            sPsum[row0 * 2 + warpS] = sum0;
            sPsum[row1 * 2 + warpS] = sum1;
        }
        #pragma unroll
        for (int nt = 0; nt < 4; nt++) {
            int colb = warpS * 32 + nt * 8 + cc;
            unsigned short h0, l0, h1, l1, h2, l2, h3, l3;
            bsplit(sacc[nt][0], h0, l0); bsplit(sacc[nt][1], h1, l1);
            bsplit(sacc[nt][2], h2, l2); bsplit(sacc[nt][3], h3, l3);
            *(uint32_t*)&pH[row0 * 72 + colb] = pack2(h0, h1);
            *(uint32_t*)&pL[row0 * 72 + colb] = pack2(l0, l1);
            *(uint32_t*)&pH[row1 * 72 + colb] = pack2(h2, h3);
            *(uint32_t*)&pL[row1 * 72 + colb] = pack2(l2, l3);
        }
        __syncthreads();

        lreg0 = lreg0 * scl0 + sPsum[row0 * 2] + sPsum[row0 * 2 + 1];
        lreg1 = lreg1 * scl1 + sPsum[row1 * 2] + sPsum[row1 * 2 + 1];
        #pragma unroll
        for (int i = 0; i < 4; i++)
            #pragma unroll
            for (int j = 0; j < 4; j++) {
                ctx[i][j][0] *= scl0; ctx[i][j][1] *= scl0;
                ctx[i][j][2] *= scl1; ctx[i][j][3] *= scl1;
            }

        // context GEMM (reuse E chunks); prefetch next tile after ch0
        #pragma unroll
        for (int ch = 0; ch < 4; ch++) {
            uint32_t ehb = base + O_E + ch * 18432;
            uint32_t elb = ehb + 9216;
            #pragma unroll
            for (int ks = 0; ks < 4; ks++) {
                int ac = ks * 16 + cc;
                int ar = warpT * 16 + r;
                uint32_t aH[4], aL[4];
                aH[0] = *(uint32_t*)&pH[ar * 72 + ac];
                aH[1] = *(uint32_t*)&pH[(ar + 8) * 72 + ac];
                aH[2] = *(uint32_t*)&pH[ar * 72 + ac + 8];
                aH[3] = *(uint32_t*)&pH[(ar + 8) * 72 + ac + 8];
                aL[0] = *(uint32_t*)&pL[ar * 72 + ac];
                aL[1] = *(uint32_t*)&pL[(ar + 8) * 72 + ac];
                aL[2] = *(uint32_t*)&pL[ar * 72 + ac + 8];
                aL[3] = *(uint32_t*)&pL[(ar + 8) * 72 + ac + 8];
                uint32_t lrow = (uint32_t)(ks * 16 + (lane & 15));
                uint32_t lcol0 = (uint32_t)(warpS * 32 + ((lane >> 4) << 3));
                #pragma unroll
                for (int pair = 0; pair < 2; pair++) {
                    uint32_t off = (lrow * 72 + lcol0 + pair * 16) * 2;
                    uint32_t bh0, bh1, bh2, bh3, bl0, bl1, bl2, bl3;
                    ldsm_x4_t(bh0, bh1, bh2, bh3, ehb + off);
                    ldsm_x4_t(bl0, bl1, bl2, bl3, elb + off);
                    uint32_t bH0[2] = {bh0, bh1}, bH1[2] = {bh2, bh3};
                    uint32_t bL0[2] = {bl0, bl1}, bL1[2] = {bl2, bl3};
                    int nt = pair * 2;
                    mma16816(ctx[ch][nt], aH, bH0);
                    mma16816(ctx[ch][nt], aH, bL0);
                    mma16816(ctx[ch][nt], aL, bH0);
                    mma16816(ctx[ch][nt + 1], aH, bH1);
                    mma16816(ctx[ch][nt + 1], aH, bL1);
                    mma16816(ctx[ch][nt + 1], aL, bH1);
                }
            }
            if (ch == 0) {
                __syncthreads();   // all warps done reading E0 (and past score)
                if (have_next) {
                    stage_chunk(base, 0, 0, dpBase, encBase, s0 + 64, tid);
                    CP_COMMIT();
                }
            }
        }
        // no end-of-tile sync: next tile's first barrier covers E1..E3 + p.
    }

    // write partials (fp32)
    size_t pmBase = (((size_t)slice * Bb + b) * Tt) + t0;
    if (warpS == 0 && (lane & 3) == 0) {
        g_pm[pmBase + row0] = mreg0;
        g_pm[pmBase + row1] = mreg1;
        g_pl[pmBase + row0] = lreg0;
        g_pl[pmBase + row1] = lreg1;
    }
    int t = t0 + row0;
    size_t obase = (((size_t)slice * Bb + b) * Tt + t) * 256;
    #pragma unroll
    for (int ch = 0; ch < 4; ch++) {
        #pragma unroll
        for (int nt = 0; nt < 4; nt++) {
            int e = ch * 64 + warpS * 32 + nt * 8 + cc;
            *(float2*)&g_pctx[obase + e] =
                make_float2(ctx[ch][nt][0], ctx[ch][nt][1]);
            *(float2*)&g_pctx[obase + 8 * 256 + e] =
                make_float2(ctx[ch][nt][2], ctx[ch][nt][3]);
        }
    }
}

// ---------------------------------------------------------------------------
extern "C" void kernel_launch(void* const* d_in, const int* in_sizes, int n_in,
                              void* d_out, int out_size)
{
    (void)in_sizes; (void)n_in; (void)out_size;
    const float* enc = (const float*)d_in[0];
    const float* dec = (const float*)d_in[1];
    const unsigned char* mask = (const unsigned char*)d_in[2];
    const float* W_enc = (const float*)d_in[3];
    const float* W_fin = (const float*)d_in[4];
    float* out = (float*)d_out;

    void *pDpH, *pDpL, *pWeH, *pWeL, *pWfH, *pWfL;
    cudaGetSymbolAddress(&pDpH, g_dpH);
    cudaGetSymbolAddress(&pDpL, g_dpL);
    cudaGetSymbolAddress(&pWeH, g_WencH);
    cudaGetSymbolAddress(&pWeL, g_WencL);
    cudaGetSymbolAddress(&pWfH, g_WfinTH);
    cudaGetSymbolAddress(&pWfL, g_WfinTL);

    cudaFuncSetAttribute((const void*)mma_gemm1_kernel,
                         cudaFuncAttributeMaxDynamicSharedMemorySize, PG_TOTAL);
    cudaFuncSetAttribute((const void*)mma_gemm3_fused,
                         cudaFuncAttributeMaxDynamicSharedMemorySize, PG_TOTAL);
    cudaFuncSetAttribute((const void*)attn_kernel,
                         cudaFuncAttributeMaxDynamicSharedMemorySize, A_TOTAL);

    detect_lengths_kernel<<<1, 256>>>(mask);
    prep_convert_kernel<<<1024, 256>>>(enc, W_enc, W_fin);

    // GEMM1': decproj = dec(fp32) @ W_enc^T, dec converted during staging
    dim3 g1(2, 128);
    mma_gemm1_kernel<<<g1, 256, PG_TOTAL>>>(
        dec,
        (const __nv_bfloat16*)pWeH, (const __nv_bfloat16*)pWeL,
        (__nv_bfloat16*)pDpH, (__nv_bfloat16*)pDpL);

    dim3 g2(Tt / 64, Bb, NSLICE);
    attn_kernel<<<g2, 256, A_TOTAL>>>();

    // GEMM3 fused with combine (weights computed in-kernel)
    dim3 g3(2, 128);
    mma_gemm3_fused<<<g3, 256, PG_TOTAL>>>(
        dec,
        (const __nv_bfloat16*)pWfH, (const __nv_bfloat16*)pWfL,
        out);
}

// round 13
// speedup vs baseline: 1.7035x; 1.1364x over previous
#include <cuda_runtime.h>
#include <cuda_bf16.h>
#include <math.h>
#include <stdint.h>

#define Bb 16
#define Ss 2048
#define Tt 1024
#define Ee 256
#define Dd 256
#define NSLICE 4
#define SLICE_S 512
#define MTOT (Bb * Tt)   // 16384

// ---------------------------------------------------------------------------
// Scratch (allocation-free device globals), bf16 hi/lo split representations.
// ---------------------------------------------------------------------------
__device__ __nv_bfloat16 g_encH[Bb * Ss * Ee];
__device__ __nv_bfloat16 g_encL[Bb * Ss * Ee];
__device__ __nv_bfloat16 g_dpH[Bb * Tt * Ee];     // decproj hi
__device__ __nv_bfloat16 g_dpL[Bb * Tt * Ee];     // decproj lo
__device__ __nv_bfloat16 g_WfinTH[Dd * (Ee + Dd)];
__device__ __nv_bfloat16 g_WfinTL[Dd * (Ee + Dd)];
__device__ int g_lengths[Bb];
__device__ float g_pctx[NSLICE * MTOT * Ee];      // fp32 split-KV partials
__device__ float g_pm[NSLICE * MTOT];
__device__ float g_pl[NSLICE * MTOT];

// ---------------------------------------------------------------------------
// Helpers
// ---------------------------------------------------------------------------
__device__ __forceinline__ uint32_t smem_u32(const void* p) {
    uint32_t a;
    asm("{ .reg .u64 t; cvta.to.shared.u64 t, %1; cvt.u32.u64 %0, t; }"
        : "=r"(a) : "l"(p));
    return a;
}

__device__ __forceinline__ void mma16816(float* d, const uint32_t* a,
                                         const uint32_t* b) {
    asm volatile(
        "mma.sync.aligned.m16n8k16.row.col.f32.bf16.bf16.f32 "
        "{%0,%1,%2,%3}, {%4,%5,%6,%7}, {%8,%9}, {%0,%1,%2,%3};"
        : "+f"(d[0]), "+f"(d[1]), "+f"(d[2]), "+f"(d[3])
        : "r"(a[0]), "r"(a[1]), "r"(a[2]), "r"(a[3]), "r"(b[0]), "r"(b[1]));
}

__device__ __forceinline__ void ldsm_x4_t(uint32_t& r0, uint32_t& r1,
                                          uint32_t& r2, uint32_t& r3,
                                          uint32_t addr) {
    asm volatile("ldmatrix.sync.aligned.m8n8.x4.trans.shared.b16 "
                 "{%0,%1,%2,%3}, [%4];"
                 : "=r"(r0), "=r"(r1), "=r"(r2), "=r"(r3) : "r"(addr));
}

__device__ __forceinline__ void cp16(uint32_t dst, const void* src) {
    asm volatile("cp.async.cg.shared.global [%0], [%1], 16;"
                 :: "r"(dst), "l"(src));
}
#define CP_COMMIT() asm volatile("cp.async.commit_group;")
#define CP_WAIT(N)  asm volatile("cp.async.wait_group %0;" :: "n"(N))

__device__ __forceinline__ void bsplit(float x, unsigned short& h,
                                       unsigned short& l) {
    __nv_bfloat16 hb = __float2bfloat16(x);
    __nv_bfloat16 lb = __float2bfloat16(x - __bfloat162float(hb));
    h = *(unsigned short*)&hb;
    l = *(unsigned short*)&lb;
}

__device__ __forceinline__ uint32_t pack2(unsigned short a, unsigned short b) {
    return (uint32_t)a | ((uint32_t)b << 16);
}

// ---------------------------------------------------------------------------
// Pipelined GEMM smem: 32-wide k-chunks, stride 40 shorts (80 B) per row,
// double-buffered. Buffer = 4 matrices (Ah,Al,Bh,Bl) x 128 rows x 80 B.
// ---------------------------------------------------------------------------
#define PG_MAT   10240          // 128 * 80
#define PG_BUF   (4 * PG_MAT)   // 40960
#define PG_TOTAL (2 * PG_BUF)   // 81920
#define PG_AH 0
#define PG_AL PG_MAT
#define PG_BH (2 * PG_MAT)
#define PG_BL (3 * PG_MAT)

// stage fp32 rows into split bf16 hi/lo smem (LDG + split + STS)
__device__ __forceinline__ void stage_f32(char* dyn, int buf, int matoff,
                                          int r0, const float* __restrict__ Af,
                                          int ldk, int kc, int tid)
{
    __nv_bfloat16* sH = (__nv_bfloat16*)(dyn + buf * PG_BUF + matoff);
    __nv_bfloat16* sL = sH + PG_MAT / 2;   // AL/BL follow AH/BH by PG_MAT
    #pragma unroll
    for (int u = 0; u < 2; u++) {
        int f = tid + u * 256;
        int rr = f >> 2, c = f & 3;
        const float* p = &Af[(size_t)(r0 + rr) * ldk + kc + c * 8];
        float4 a = *(const float4*)p;
        float4 b = *(const float4*)(p + 4);
        ushort4 hv1, lv1, hv2, lv2;
        bsplit(a.x, hv1.x, lv1.x); bsplit(a.y, hv1.y, lv1.y);
        bsplit(a.z, hv1.z, lv1.z); bsplit(a.w, hv1.w, lv1.w);
        bsplit(b.x, hv2.x, lv2.x); bsplit(b.y, hv2.y, lv2.y);
        bsplit(b.z, hv2.z, lv2.z); bsplit(b.w, hv2.w, lv2.w);
        *(ushort4*)&sH[rr * 40 + c * 8] = hv1;
        *(ushort4*)&sH[rr * 40 + c * 8 + 4] = hv2;
        *(ushort4*)&sL[rr * 40 + c * 8] = lv1;
        *(ushort4*)&sL[rr * 40 + c * 8 + 4] = lv2;
    }
}

// ---------------------------------------------------------------------------
// MEGA kernel: CTA roles
//   bid 0..255   : GEMM1' (decproj = dec @ W_enc^T), both operands fp32,
//                  converted during staging. Grid (2 n-tiles x 128 m-tiles).
//   bid 256      : detect_lengths from mask
//   bid 257..1023: enc + W_fin fp32 -> bf16 hi/lo conversion (grid-stride)
// ---------------------------------------------------------------------------
__global__ __launch_bounds__(256, 2)
void mega_prep_gemm1(const float* __restrict__ dec,
                     const float* __restrict__ enc,
                     const float* __restrict__ Wenc,
                     const float* __restrict__ Wfin,
                     const unsigned char* __restrict__ mask,
                     __nv_bfloat16* __restrict__ CH,
                     __nv_bfloat16* __restrict__ CL)
{
    extern __shared__ char dyn[];
    int bid = blockIdx.x;
    int tid = threadIdx.x;

    if (bid >= 257) {
        // ------------------- conversion workers ---------------------------
        int w = (bid - 257) * 256 + tid;
        int stride = 767 * 256;
        const int NE4 = (Bb * Ss * Ee) / 4;
        for (int i = w; i < NE4; i += stride) {
            float4 v = ((const float4*)enc)[i];
            ushort4 hv, lv;
            bsplit(v.x, hv.x, lv.x); bsplit(v.y, hv.y, lv.y);
            bsplit(v.z, hv.z, lv.z); bsplit(v.w, hv.w, lv.w);
            ((ushort4*)g_encH)[i] = hv;
            ((ushort4*)g_encL)[i] = lv;
        }
        for (int i = w; i < 256 * 512; i += stride) {
            int d = i >> 9, f = i & 511;
            unsigned short h, l;
            bsplit(Wfin[f * 256 + d], h, l);
            *(unsigned short*)&g_WfinTH[i] = h;
            *(unsigned short*)&g_WfinTL[i] = l;
        }
        return;
    }

    if (bid == 256) {
        // ------------------- detect lengths -------------------------------
        __shared__ int s_flag;
        __shared__ int s_cnt[Bb];
        if (tid == 0) s_flag = 0;
        if (tid < Bb) s_cnt[tid] = 0;
        __syncthreads();
        int local = 0;
        for (int i = tid; i < Bb * Ss; i += 256)
            if ((i & 3) != 0 && mask[i] != 0) local = 1;
        if (local) atomicOr(&s_flag, 1);
        __syncthreads();
        bool isU8 = (s_flag != 0);
        int row = tid >> 4, part = tid & 15;
        int cnt = 0;
        if (isU8) {
            const unsigned char* p = mask + row * Ss + part * 128;
            #pragma unroll 4
            for (int e = 0; e < 128; e++) cnt += (p[e] != 0);
        } else {
            const int* p = ((const int*)mask) + row * Ss + part * 128;
            #pragma unroll 4
            for (int e = 0; e < 128; e++) cnt += (p[e] != 0);
        }
        atomicAdd(&s_cnt[row], cnt);
        __syncthreads();
        if (tid < Bb) g_lengths[tid] = s_cnt[tid];
        return;
    }

    // ----------------------- GEMM1' ---------------------------------------
    int lane = tid & 31, wid = tid >> 5;
    int warpM = wid & 3, warpN = wid >> 2;
    int m0 = (bid >> 1) * 128, n0 = (bid & 1) * 128;
    int r = lane >> 2, cc = (lane & 3) * 2;

    float acc[2][8][4];
    #pragma unroll
    for (int i = 0; i < 2; i++)
        #pragma unroll
        for (int j = 0; j < 8; j++)
            #pragma unroll
            for (int q = 0; q < 4; q++) acc[i][j][q] = 0.f;

    // prologue: stage chunk 0 (A from dec fp32, B from W_enc fp32 [e][d])
    stage_f32(dyn, 0, PG_AH, m0, dec, 256, 0, tid);
    stage_f32(dyn, 0, PG_BH, n0, Wenc, 256, 0, tid);
    __syncthreads();

    for (int ch = 0; ch < 8; ch++) {
        const __nv_bfloat16* sAH =
            (const __nv_bfloat16*)(dyn + (ch & 1) * PG_BUF + PG_AH);
        const __nv_bfloat16* sAL =
            (const __nv_bfloat16*)(dyn + (ch & 1) * PG_BUF + PG_AL);
        const __nv_bfloat16* sBH =
            (const __nv_bfloat16*)(dyn + (ch & 1) * PG_BUF + PG_BH);
        const __nv_bfloat16* sBL =
            (const __nv_bfloat16*)(dyn + (ch & 1) * PG_BUF + PG_BL);

        if (ch < 7) {
            stage_f32(dyn, (ch + 1) & 1, PG_AH, m0, dec, 256, (ch + 1) * 32, tid);
            stage_f32(dyn, (ch + 1) & 1, PG_BH, n0, Wenc, 256, (ch + 1) * 32, tid);
        }

        #pragma unroll
        for (int ks = 0; ks < 2; ks++) {
            int ac = ks * 16 + cc;
            uint32_t aH[2][4], aL[2][4];
            #pragma unroll
            for (int mt = 0; mt < 2; mt++) {
                int ar = warpM * 32 + mt * 16 + r;
                aH[mt][0] = *(uint32_t*)&sAH[ar * 40 + ac];
                aH[mt][1] = *(uint32_t*)&sAH[(ar + 8) * 40 + ac];
                aH[mt][2] = *(uint32_t*)&sAH[ar * 40 + ac + 8];
                aH[mt][3] = *(uint32_t*)&sAH[(ar + 8) * 40 + ac + 8];
                aL[mt][0] = *(uint32_t*)&sAL[ar * 40 + ac];
                aL[mt][1] = *(uint32_t*)&sAL[(ar + 8) * 40 + ac];
                aL[mt][2] = *(uint32_t*)&sAL[ar * 40 + ac + 8];
                aL[mt][3] = *(uint32_t*)&sAL[(ar + 8) * 40 + ac + 8];
            }
            #pragma unroll
            for (int nt = 0; nt < 8; nt++) {
                int bn = warpN * 64 + nt * 8 + r;
                uint32_t bH[2], bL[2];
                bH[0] = *(uint32_t*)&sBH[bn * 40 + ac];
                bH[1] = *(uint32_t*)&sBH[bn * 40 + ac + 8];
                bL[0] = *(uint32_t*)&sBL[bn * 40 + ac];
                bL[1] = *(uint32_t*)&sBL[bn * 40 + ac + 8];
                #pragma unroll
                for (int mt = 0; mt < 2; mt++) {
                    mma16816(acc[mt][nt], aH[mt], bH);
                    mma16816(acc[mt][nt], aH[mt], bL);
                    mma16816(acc[mt][nt], aL[mt], bH);
                }
            }
        }
        __syncthreads();   // compute(ch) done before buf (ch&1) reused at ch+2
    }

    #pragma unroll
    for (int mt = 0; mt < 2; mt++) {
        #pragma unroll
        for (int nt = 0; nt < 8; nt++) {
            int m = m0 + warpM * 32 + mt * 16 + r;
            int n = n0 + warpN * 64 + nt * 8 + cc;
            unsigned short h0, l0, h1, l1, h2, l2, h3, l3;
            bsplit(acc[mt][nt][0], h0, l0); bsplit(acc[mt][nt][1], h1, l1);
            bsplit(acc[mt][nt][2], h2, l2); bsplit(acc[mt][nt][3], h3, l3);
            *(uint32_t*)&CH[(size_t)m * 256 + n] = pack2(h0, h1);
            *(uint32_t*)&CL[(size_t)m * 256 + n] = pack2(l0, l1);
            *(uint32_t*)&CH[(size_t)(m + 8) * 256 + n] = pack2(h2, h3);
            *(uint32_t*)&CL[(size_t)(m + 8) * 256 + n] = pack2(l2, l3);
        }
    }
}

// ---------------------------------------------------------------------------
// GEMM3 fused with combine (round-12 version, unchanged)
// ---------------------------------------------------------------------------
__global__ __launch_bounds__(256, 2)
void mma_gemm3_fused(const float* __restrict__ decf,
                     const __nv_bfloat16* __restrict__ BTH,
                     const __nv_bfloat16* __restrict__ BTL,
                     float* __restrict__ out)
{
    extern __shared__ char dyn[];
    __shared__ float wsm[128][4];
    uint32_t base = smem_u32(dyn);

    int tid = threadIdx.x, lane = tid & 31, wid = tid >> 5;
    int warpM = wid & 3, warpN = wid >> 2;
    int m0 = blockIdx.y * 128, n0 = blockIdx.x * 128;
    int r = lane >> 2, cc = (lane & 3) * 2;
    int nsl = min(NSLICE, (g_lengths[m0 >> 10] + SLICE_S - 1) / SLICE_S);

    if (tid < 128) {
        int m = m0 + tid;
        float mv[4], lv[4];
        float M = -1e30f;
        for (int s = 0; s < nsl; s++) {
            mv[s] = g_pm[s * MTOT + m];
            lv[s] = g_pl[s * MTOT + m];
            M = fmaxf(M, mv[s]);
        }
        float L = 0.f, ws[4];
        for (int s = 0; s < nsl; s++) {
            float e = __expf(mv[s] - M);
            ws[s] = e;
            L += e * lv[s];
        }
        float inv = 1.0f / L;
        #pragma unroll
        for (int s = 0; s < 4; s++)
            wsm[tid][s] = (s < nsl) ? ws[s] * inv : 0.f;
    }
    __syncthreads();

    float wreg[2][4];
    #pragma unroll
    for (int u = 0; u < 2; u++) {
        int rr = (tid + u * 256) >> 2;
        #pragma unroll
        for (int s = 0; s < 4; s++)
            wreg[u][s] = wsm[rr][s];
    }

    float acc[2][8][4];
    #pragma unroll
    for (int i = 0; i < 2; i++)
        #pragma unroll
        for (int j = 0; j < 8; j++)
            #pragma unroll
            for (int q = 0; q < 4; q++) acc[i][j][q] = 0.f;

    auto stage = [&](int ch, int buf) {
        uint32_t bb = base + buf * PG_BUF;
        int kc = ch * 32;
        #pragma unroll
        for (int u = 0; u < 2; u++) {
            int f = tid + u * 256;
            int rr = f >> 2, c = f & 3;
            uint32_t doff = rr * 80 + c * 16;
            size_t gb = (size_t)(n0 + rr) * 512 + kc + c * 8;
            cp16(bb + PG_BH + doff, BTH + gb);
            cp16(bb + PG_BL + doff, BTL + gb);
        }
        if (ch >= 8) {
            stage_f32(dyn, buf, PG_AH, m0, decf, 256, kc - 256, tid);
        } else {
            __nv_bfloat16* sAH = (__nv_bfloat16*)(dyn + buf * PG_BUF + PG_AH);
            __nv_bfloat16* sAL = (__nv_bfloat16*)(dyn + buf * PG_BUF + PG_AL);
            #pragma unroll
            for (int u = 0; u < 2; u++) {
                int f = tid + u * 256;
                int rr = f >> 2, c8 = f & 3;
                int m = m0 + rr;
                float v[8] = {0, 0, 0, 0, 0, 0, 0, 0};
                for (int s = 0; s < nsl; s++) {
                    float w = wreg[u][s];
                    const float* p =
                        &g_pctx[((size_t)s * MTOT + m) * 256 + kc + c8 * 8];
                    float4 a = *(const float4*)p;
                    float4 bq = *(const float4*)(p + 4);
                    v[0] += w * a.x;  v[1] += w * a.y;
                    v[2] += w * a.z;  v[3] += w * a.w;
                    v[4] += w * bq.x; v[5] += w * bq.y;
                    v[6] += w * bq.z; v[7] += w * bq.w;
                }
                ushort4 hv1, lv1, hv2, lv2;
                bsplit(v[0], hv1.x, lv1.x); bsplit(v[1], hv1.y, lv1.y);
                bsplit(v[2], hv1.z, lv1.z); bsplit(v[3], hv1.w, lv1.w);
                bsplit(v[4], hv2.x, lv2.x); bsplit(v[5], hv2.y, lv2.y);
                bsplit(v[6], hv2.z, lv2.z); bsplit(v[7], hv2.w, lv2.w);
                *(ushort4*)&sAH[rr * 40 + c8 * 8] = hv1;
                *(ushort4*)&sAH[rr * 40 + c8 * 8 + 4] = hv2;
                *(ushort4*)&sAL[rr * 40 + c8 * 8] = lv1;
                *(ushort4*)&sAL[rr * 40 + c8 * 8 + 4] = lv2;
            }
        }
    };

    stage(0, 0);
    CP_COMMIT();

    for (int ch = 0; ch < 16; ch++) {
        CP_WAIT(0);
        __syncthreads();
        if (ch < 15) {
            stage(ch + 1, (ch + 1) & 1);
            CP_COMMIT();
        }
        const __nv_bfloat16* sAH =
            (const __nv_bfloat16*)(dyn + (ch & 1) * PG_BUF + PG_AH);
        const __nv_bfloat16* sAL =
            (const __nv_bfloat16*)(dyn + (ch & 1) * PG_BUF + PG_AL);
        const __nv_bfloat16* sBH =
            (const __nv_bfloat16*)(dyn + (ch & 1) * PG_BUF + PG_BH);
        const __nv_bfloat16* sBL =
            (const __nv_bfloat16*)(dyn + (ch & 1) * PG_BUF + PG_BL);

        #pragma unroll
        for (int ks = 0; ks < 2; ks++) {
            int ac = ks * 16 + cc;
            uint32_t aH[2][4], aL[2][4];
            #pragma unroll
            for (int mt = 0; mt < 2; mt++) {
                int ar = warpM * 32 + mt * 16 + r;
                aH[mt][0] = *(uint32_t*)&sAH[ar * 40 + ac];
                aH[mt][1] = *(uint32_t*)&sAH[(ar + 8) * 40 + ac];
                aH[mt][2] = *(uint32_t*)&sAH[ar * 40 + ac + 8];
                aH[mt][3] = *(uint32_t*)&sAH[(ar + 8) * 40 + ac + 8];
                aL[mt][0] = *(uint32_t*)&sAL[ar * 40 + ac];
                aL[mt][1] = *(uint32_t*)&sAL[(ar + 8) * 40 + ac];
                aL[mt][2] = *(uint32_t*)&sAL[ar * 40 + ac + 8];
                aL[mt][3] = *(uint32_t*)&sAL[(ar + 8) * 40 + ac + 8];
            }
            #pragma unroll
            for (int nt = 0; nt < 8; nt++) {
                int bn = warpN * 64 + nt * 8 + r;
                uint32_t bH[2], bL[2];
                bH[0] = *(uint32_t*)&sBH[bn * 40 + ac];
                bH[1] = *(uint32_t*)&sBH[bn * 40 + ac + 8];
                bL[0] = *(uint32_t*)&sBL[bn * 40 + ac];
                bL[1] = *(uint32_t*)&sBL[bn * 40 + ac + 8];
                #pragma unroll
                for (int mt = 0; mt < 2; mt++) {
                    mma16816(acc[mt][nt], aH[mt], bH);
                    mma16816(acc[mt][nt], aH[mt], bL);
                    mma16816(acc[mt][nt], aL[mt], bH);
                }
            }
        }
    }

    #pragma unroll
    for (int mt = 0; mt < 2; mt++) {
        #pragma unroll
        for (int nt = 0; nt < 8; nt++) {
            int m = m0 + warpM * 32 + mt * 16 + r;
            int n = n0 + warpN * 64 + nt * 8 + cc;
            float2 v0 = make_float2(tanhf(acc[mt][nt][0]), tanhf(acc[mt][nt][1]));
            float2 v1 = make_float2(tanhf(acc[mt][nt][2]), tanhf(acc[mt][nt][3]));
            *(float2*)&out[(size_t)m * 256 + n] = v0;
            *(float2*)&out[(size_t)(m + 8) * 256 + n] = v1;
        }
    }
}

// ---------------------------------------------------------------------------
// Fused flash attention (round-12 committed version, unchanged)
// ---------------------------------------------------------------------------
#define O_AH0 0
#define O_AL0 9216
#define O_AH1 18432
#define O_AL1 27648
#define O_E   36864
#define O_PMAX 110592
#define O_PSUM 111104
#define A_TOTAL 111616

__device__ __forceinline__ void stage_chunk(uint32_t base, int abuf, int ch,
                                            size_t dpBase, size_t encBase,
                                            int s0, int tid)
{
    uint32_t ah = base + (abuf ? O_AH1 : O_AH0);
    uint32_t al = ah + 9216;
    uint32_t eh = base + O_E + ch * 18432;
    uint32_t el = eh + 9216;
    int kc = ch * 64;
    #pragma unroll
    for (int u = 0; u < 2; u++) {
        int f = tid + u * 256;
        int rr = f >> 3, c = f & 7;
        uint32_t doff = rr * 144 + c * 16;
        size_t ga = dpBase + (size_t)rr * 256 + kc + c * 8;
        size_t ge = encBase + (size_t)(s0 + rr) * 256 + kc + c * 8;
        cp16(ah + doff, g_dpH + ga);
        cp16(al + doff, g_dpL + ga);
        cp16(eh + doff, g_encH + ge);
        cp16(el + doff, g_encL + ge);
    }
}

__global__ __launch_bounds__(256, 2)
void attn_kernel()
{
    extern __shared__ char dyn[];
    uint32_t base = smem_u32(dyn);
    float* sPmax = (float*)(dyn + O_PMAX);
    float* sPsum = (float*)(dyn + O_PSUM);
    __nv_bfloat16* pH = (__nv_bfloat16*)(dyn + O_AH1);
    __nv_bfloat16* pL = (__nv_bfloat16*)(dyn + O_AL1);

    int tid = threadIdx.x, lane = tid & 31, wid = tid >> 5;
    int warpT = wid & 3;
    int warpS = wid >> 2;
    int r = lane >> 2, cc = (lane & 3) * 2;
    int b = blockIdx.y;
    int t0 = blockIdx.x * 64;
    int slice = blockIdx.z;
    int len = g_lengths[b];

    int sbeg = slice * SLICE_S;
    if (sbeg >= len) return;
    int send = min(sbeg + SLICE_S, len);

    size_t dpBase = ((size_t)b * Tt + t0) * 256;
    size_t encBase = (size_t)b * Ss * 256;

    int row0 = warpT * 16 + r;
    int row1 = row0 + 8;
    float mreg0 = -1e30f, mreg1 = -1e30f;
    float lreg0 = 0.f, lreg1 = 0.f;

    float ctx[4][4][4];
    #pragma unroll
    for (int i = 0; i < 4; i++)
        #pragma unroll
        for (int j = 0; j < 4; j++)
            #pragma unroll
            for (int q = 0; q < 4; q++) ctx[i][j][q] = 0.f;

    stage_chunk(base, 0, 0, dpBase, encBase, sbeg, tid);
    CP_COMMIT();

    for (int s0 = sbeg; s0 < send; s0 += 64) {
        bool have_next = (s0 + 64 < send);

        float sacc[4][4];
        #pragma unroll
        for (int j = 0; j < 4; j++)
            #pragma unroll
            for (int q = 0; q < 4; q++) sacc[j][q] = 0.f;

        #pragma unroll
        for (int kch = 0; kch < 4; kch++) {
            CP_WAIT(0);
            __syncthreads();
            if (kch < 3) {
                stage_chunk(base, (kch + 1) & 1, kch + 1, dpBase, encBase,
                            s0, tid);
                CP_COMMIT();
            }

            const __nv_bfloat16* sAH =
                (const __nv_bfloat16*)(dyn + ((kch & 1) ? O_AH1 : O_AH0));
            const __nv_bfloat16* sAL = sAH + 4608;
            const __nv_bfloat16* sBH =
                (const __nv_bfloat16*)(dyn + O_E + kch * 18432);
            const __nv_bfloat16* sBL = sBH + 4608;

            #pragma unroll
            for (int ks = 0; ks < 4; ks++) {
                int ac = ks * 16 + cc;
                int ar = warpT * 16 + r;
                uint32_t aH[4], aL[4];
                aH[0] = *(uint32_t*)&sAH[ar * 72 + ac];
                aH[1] = *(uint32_t*)&sAH[(ar + 8) * 72 + ac];
                aH[2] = *(uint32_t*)&sAH[ar * 72 + ac + 8];
                aH[3] = *(uint32_t*)&sAH[(ar + 8) * 72 + ac + 8];
                aL[0] = *(uint32_t*)&sAL[ar * 72 + ac];
                aL[1] = *(uint32_t*)&sAL[(ar + 8) * 72 + ac];
                aL[2] = *(uint32_t*)&sAL[ar * 72 + ac + 8];
                aL[3] = *(uint32_t*)&sAL[(ar + 8) * 72 + ac + 8];
                #pragma unroll
                for (int nt = 0; nt < 4; nt++) {
                    int bn = warpS * 32 + nt * 8 + r;
                    uint32_t bH[2], bL[2];
                    bH[0] = *(uint32_t*)&sBH[bn * 72 + ac];
                    bH[1] = *(uint32_t*)&sBH[bn * 72 + ac + 8];
                    bL[0] = *(uint32_t*)&sBL[bn * 72 + ac];
                    bL[1] = *(uint32_t*)&sBL[bn * 72 + ac + 8];
                    mma16816(sacc[nt], aH, bH);
                    mma16816(sacc[nt], aH, bL);
                    mma16816(sacc[nt], aL, bH);
                }
            }
        }

        // register softmax
        float rm0 = -1e30f, rm1 = -1e30f;
        #pragma unroll
        for (int nt = 0; nt < 4; nt++) {
            int cg = s0 + warpS * 32 + nt * 8 + cc;
            if (cg >= len)     { sacc[nt][0] = -1e30f; sacc[nt][2] = -1e30f; }
            if (cg + 1 >= len) { sacc[nt][1] = -1e30f; sacc[nt][3] = -1e30f; }
            rm0 = fmaxf(rm0, fmaxf(sacc[nt][0], sacc[nt][1]));
            rm1 = fmaxf(rm1, fmaxf(sacc[nt][2], sacc[nt][3]));
        }
        rm0 = fmaxf(rm0, __shfl_xor_sync(0xffffffffu, rm0, 1));
        rm0 = fmaxf(rm0, __shfl_xor_sync(0xffffffffu, rm0, 2));
        rm1 = fmaxf(rm1, __shfl_xor_sync(0xffffffffu, rm1, 1));
        rm1 = fmaxf(rm1, __shfl_xor_sync(0xffffffffu, rm1, 2));
        if ((lane & 3) == 0) {
            sPmax[row0 * 2 + warpS] = rm0;
            sPmax[row1 * 2 + warpS] = rm1;
        }
        __syncthreads();

        float mN0 = fmaxf(mreg0, fmaxf(sPmax[row0 * 2], sPmax[row0 * 2 + 1]));
        float mN1 = fmaxf(mreg1, fmaxf(sPmax[row1 * 2], sPmax[row1 * 2 + 1]));
        float scl0 = __expf(mreg0 - mN0);
        float scl1 = __expf(mreg1 - mN1);
        mreg0 = mN0; mreg1 = mN1;

        float sum0 = 0.f, sum1 = 0.f;
        #pragma unroll
        for (int nt = 0; nt < 4; nt++) {
            sacc[nt][0] = __expf(sacc[nt][0] - mN0);
            sacc[nt][1] = __expf(sacc[nt][1] - mN0);
            sacc[nt][2] = __expf(sacc[nt][2] - mN1);
            sacc[nt][3] = __expf(sacc[nt][3] - mN1);
            sum0 += sacc[nt][0] + sacc[nt][1];
            sum1 += sacc[nt][2] + sacc[nt][3];
        }
        sum0 += __shfl_xor_sync(0xffffffffu, sum0, 1);
        sum0 += __shfl_xor_sync(0xffffffffu, sum0, 2);
        sum1 += __shfl_xor_sync(0xffffffffu, sum1, 1);
        sum1 += __shfl_xor_sync(0xffffffffu, sum1, 2);
        if ((lane & 3) == 0) {
            sPsum[row0 * 2 + warpS] = sum0;
            sPsum[row1 * 2 + warpS] = sum1;
        }
        #pragma unroll
        for (int nt = 0; nt < 4; nt++) {
            int colb = warpS * 32 + nt * 8 + cc;
            unsigned short h0, l0, h1, l1, h2, l2, h3, l3;
            bsplit(sacc[nt][0], h0, l0); bsplit(sacc[nt][1], h1, l1);
            bsplit(sacc[nt][2], h2, l2); bsplit(sacc[nt][3], h3, l3);
            *(uint32_t*)&pH[row0 * 72 + colb] = pack2(h0, h1);
            *(uint32_t*)&pL[row0 * 72 + colb] = pack2(l0, l1);
            *(uint32_t*)&pH[row1 * 72 + colb] = pack2(h2, h3);
            *(uint32_t*)&pL[row1 * 72 + colb] = pack2(l2, l3);
        }
        __syncthreads();

        lreg0 = lreg0 * scl0 + sPsum[row0 * 2] + sPsum[row0 * 2 + 1];
        lreg1 = lreg1 * scl1 + sPsum[row1 * 2] + sPsum[row1 * 2 + 1];
        #pragma unroll
        for (int i = 0; i < 4; i++)
            #pragma unroll
            for (int j = 0; j < 4; j++) {
                ctx[i][j][0] *= scl0; ctx[i][j][1] *= scl0;
                ctx[i][j][2] *= scl1; ctx[i][j][3] *= scl1;
            }

        #pragma unroll
        for (int ch = 0; ch < 4; ch++) {
            uint32_t ehb = base + O_E + ch * 18432;
            uint32_t elb = ehb + 9216;
            #pragma unroll
            for (int ks = 0; ks < 4; ks++) {
                int ac = ks * 16 + cc;
                int ar = warpT * 16 + r;
                uint32_t aH[4], aL[4];
                aH[0] = *(uint32_t*)&pH[ar * 72 + ac];
                aH[1] = *(uint32_t*)&pH[(ar + 8) * 72 + ac];
                aH[2] = *(uint32_t*)&pH[ar * 72 + ac + 8];
                aH[3] = *(uint32_t*)&pH[(ar + 8) * 72 + ac + 8];
                aL[0] = *(uint32_t*)&pL[ar * 72 + ac];
                aL[1] = *(uint32_t*)&pL[(ar + 8) * 72 + ac];
                aL[2] = *(uint32_t*)&pL[ar * 72 + ac + 8];
                aL[3] = *(uint32_t*)&pL[(ar + 8) * 72 + ac + 8];
                uint32_t lrow = (uint32_t)(ks * 16 + (lane & 15));
                uint32_t lcol0 = (uint32_t)(warpS * 32 + ((lane >> 4) << 3));
                #pragma unroll
                for (int pair = 0; pair < 2; pair++) {
                    uint32_t off = (lrow * 72 + lcol0 + pair * 16) * 2;
                    uint32_t bh0, bh1, bh2, bh3, bl0, bl1, bl2, bl3;
                    ldsm_x4_t(bh0, bh1, bh2, bh3, ehb + off);
                    ldsm_x4_t(bl0, bl1, bl2, bl3, elb + off);
                    uint32_t bH0[2] = {bh0, bh1}, bH1[2] = {bh2, bh3};
                    uint32_t bL0[2] = {bl0, bl1}, bL1[2] = {bl2, bl3};
                    int nt = pair * 2;
                    mma16816(ctx[ch][nt], aH, bH0);
                    mma16816(ctx[ch][nt], aH, bL0);
                    mma16816(ctx[ch][nt], aL, bH0);
                    mma16816(ctx[ch][nt + 1], aH, bH1);
                    mma16816(ctx[ch][nt + 1], aH, bL1);
                    mma16816(ctx[ch][nt + 1], aL, bH1);
                }
            }
            if (ch == 0) {
                __syncthreads();
                if (have_next) {
                    stage_chunk(base, 0, 0, dpBase, encBase, s0 + 64, tid);
                    CP_COMMIT();
                }
            }
        }
    }

    size_t pmBase = (((size_t)slice * Bb + b) * Tt) + t0;
    if (warpS == 0 && (lane & 3) == 0) {
        g_pm[pmBase + row0] = mreg0;
        g_pm[pmBase + row1] = mreg1;
        g_pl[pmBase + row0] = lreg0;
        g_pl[pmBase + row1] = lreg1;
    }
    int t = t0 + row0;
    size_t obase = (((size_t)slice * Bb + b) * Tt + t) * 256;
    #pragma unroll
    for (int ch = 0; ch < 4; ch++) {
        #pragma unroll
        for (int nt = 0; nt < 4; nt++) {
            int e = ch * 64 + warpS * 32 + nt * 8 + cc;
            *(float2*)&g_pctx[obase + e] =
                make_float2(ctx[ch][nt][0], ctx[ch][nt][1]);
            *(float2*)&g_pctx[obase + 8 * 256 + e] =
                make_float2(ctx[ch][nt][2], ctx[ch][nt][3]);
        }
    }
}

// ---------------------------------------------------------------------------
extern "C" void kernel_launch(void* const* d_in, const int* in_sizes, int n_in,
                              void* d_out, int out_size)
{
    (void)in_sizes; (void)n_in; (void)out_size;
    const float* enc = (const float*)d_in[0];
    const float* dec = (const float*)d_in[1];
    const unsigned char* mask = (const unsigned char*)d_in[2];
    const float* W_enc = (const float*)d_in[3];
    const float* W_fin = (const float*)d_in[4];
    float* out = (float*)d_out;

    void *pDpH, *pDpL, *pWfH, *pWfL;
    cudaGetSymbolAddress(&pDpH, g_dpH);
    cudaGetSymbolAddress(&pDpL, g_dpL);
    cudaGetSymbolAddress(&pWfH, g_WfinTH);
    cudaGetSymbolAddress(&pWfL, g_WfinTL);

    cudaFuncSetAttribute((const void*)mega_prep_gemm1,
                         cudaFuncAttributeMaxDynamicSharedMemorySize, PG_TOTAL);
    cudaFuncSetAttribute((const void*)mma_gemm3_fused,
                         cudaFuncAttributeMaxDynamicSharedMemorySize, PG_TOTAL);
    cudaFuncSetAttribute((const void*)attn_kernel,
                         cudaFuncAttributeMaxDynamicSharedMemorySize, A_TOTAL);

    // kernel 1: detect + prep + GEMM1' fused (role-split CTAs)
    mega_prep_gemm1<<<1024, 256, PG_TOTAL>>>(
        dec, enc, W_enc, W_fin, mask,
        (__nv_bfloat16*)pDpH, (__nv_bfloat16*)pDpL);

    // kernel 2: split-KV attention
    dim3 g2(Tt / 64, Bb, NSLICE);
    attn_kernel<<<g2, 256, A_TOTAL>>>();

    // kernel 3: GEMM3 fused with combine
    dim3 g3(2, 128);
    mma_gemm3_fused<<<g3, 256, PG_TOTAL>>>(
        dec,
        (const __nv_bfloat16*)pWfH, (const __nv_bfloat16*)pWfL,
        out);
}